// round 10
// baseline (speedup 1.0000x reference)
#include <cuda_runtime.h>
#include <cuda_bf16.h>
#include <mma.h>
#include <math.h>
#include <stdint.h>

using namespace nvcuda;

#define NB   64
#define LL   1024
#define DM   512
#define ROWS (NB*LL)          // 65536

// ---------------- persistent bf16 hi/lo planes + fp32 scratch -------------
__device__ __nv_bfloat16 g_xh [(size_t)ROWS*DM],  g_xl [(size_t)ROWS*DM];
__device__ __nv_bfloat16 g_sh [(size_t)ROWS*DM],  g_sl [(size_t)ROWS*DM];
__device__ __nv_bfloat16 g_Wqh[DM*DM], g_Wql[DM*DM];
__device__ __nv_bfloat16 g_Wkh[DM*DM], g_Wkl[DM*DM];
__device__ __nv_bfloat16 g_Wvh[DM*DM], g_Wvl[DM*DM];
__device__ __nv_bfloat16 g_Wmh[DM*DM], g_Wml[DM*DM];
__device__ __nv_bfloat16 g_W1h[4*DM*DM], g_W1l[4*DM*DM];
__device__ __nv_bfloat16 g_W2h[2*DM*DM], g_W2l[2*DM*DM];
__device__ __nv_bfloat16 g_Qh  [(size_t)ROWS*DM], g_Ql  [(size_t)ROWS*DM];
__device__ __nv_bfloat16 g_KfTh[(size_t)ROWS*DM], g_KfTl[(size_t)ROWS*DM];
__device__ __nv_bfloat16 g_VfTh[(size_t)ROWS*DM], g_VfTl[(size_t)ROWS*DM];
__device__ __nv_bfloat16 g_KVh [(size_t)NB*DM*DM], g_KVl [(size_t)NB*DM*DM];
__device__ __nv_bfloat16 g_Mh  [(size_t)NB*DM*DM], g_Ml  [(size_t)NB*DM*DM];
__device__ __nv_bfloat16 g_m2h [(size_t)ROWS*DM], g_m2l [(size_t)ROWS*DM];
__device__ __nv_bfloat16 g_th  [(size_t)ROWS*2*DM], g_tl [(size_t)ROWS*2*DM];
__device__ float g_msg2f[(size_t)ROWS*DM];
__device__ float g_h2f  [(size_t)ROWS*DM];
__device__ float g_Ksum [NB*DM];
__device__ float g_Z    [ROWS];

enum { E_NONE=0, E_ELU1=1, E_MASK=2, E_RELU=4 };

// smem: 3 stages; each stage = Ahi(20480) Alo(20480) Bhi(10240) Blo(10240)
#define BK    32
#define LDAB  40
#define SSZ   61440
#define SMEM_BYTES 184320
#define LDST  132
#define LDST_T 264

__device__ __forceinline__ void cpa16(uint32_t dst, const void* src){
    asm volatile("cp.async.cg.shared.global [%0], [%1], 16;" :: "r"(dst), "l"(src) : "memory");
}
#define CP_COMMIT() asm volatile("cp.async.commit_group;" ::: "memory")

__device__ __forceinline__ void hilo(float x, __nv_bfloat16& h, __nv_bfloat16& l){
    h = __float2bfloat16_rn(x);
    l = __float2bfloat16_rn(x - __bfloat162float(h));
}

// =====================================================================
// bf16 3-term split NT GEMM (cp.async 3-stage): C = A @ B^T, K-major
// CTA tile 256x128, BK=32, 256 thr / 8 warps, warp tile 64x64
// =====================================================================
template<int EPI, bool TRANSC, bool CAT, bool OBF, bool OF32>
__global__ void __launch_bounds__(256)
gemm_tc(const __nv_bfloat16* __restrict__ A1h, const __nv_bfloat16* __restrict__ A1l,
        const __nv_bfloat16* __restrict__ A2h, const __nv_bfloat16* __restrict__ A2l,
        const __nv_bfloat16* __restrict__ Bh,  const __nv_bfloat16* __restrict__ Bl,
        __nv_bfloat16* __restrict__ Ch, __nv_bfloat16* __restrict__ Cl,
        float* __restrict__ Cf, const float* __restrict__ rs,
        int K, int M_batch, long long a_bs, long long b_bs, long long c_bs, int nld)
{
    extern __shared__ char smx[];
    const uint32_t sb = (uint32_t)__cvta_generic_to_shared(smx);
    const int tid  = threadIdx.x;
    const int wid  = tid >> 5;
    const int lane = tid & 31;
    const int wm   = wid & 3;          // 64-row block
    const int wn   = wid >> 2;         // 64-col block
    const int bm   = blockIdx.y * 256;
    const int bn   = blockIdx.x * 128;
    const int z    = blockIdx.z;
    const __nv_bfloat16* Abh = A1h + (size_t)z * a_bs;
    const __nv_bfloat16* Abl = A1l + (size_t)z * a_bs;
    const __nv_bfloat16* Bbh = Bh  + (size_t)z * b_bs;
    const __nv_bfloat16* Bbl = Bl  + (size_t)z * b_bs;

    wmma::fragment<wmma::accumulator,16,16,16,float> acc[4][4];
#pragma unroll
    for (int i=0;i<4;i++)
#pragma unroll
        for (int j=0;j<4;j++) wmma::fill_fragment(acc[i][j], 0.f);

    const int KT = K / BK;

    auto ISSUE = [&](int kt, int buf){
        const int k0 = kt * BK;
        const uint32_t base = sb + buf * SSZ;
#pragma unroll
        for (int p=0;p<2;p++){
#pragma unroll
            for (int i=0;i<4;i++){
                int idx = tid + i*256;
                int r = idx >> 2, c = idx & 3;
                int kk = k0 + c*8;
                const __nv_bfloat16* src;
                if (CAT){
                    const __nv_bfloat16* bp = (kk < DM) ? (p ? A1l : A1h)
                                                        : (p ? A2l : A2h);
                    int kkk = (kk < DM) ? kk : kk - DM;
                    src = bp + (size_t)(bm+r)*DM + kkk;
                } else {
                    src = (p ? Abl : Abh) + (size_t)(bm+r)*K + kk;
                }
                cpa16(base + p*20480 + r*80 + c*16, src);
            }
        }
#pragma unroll
        for (int p=0;p<2;p++){
#pragma unroll
            for (int i=0;i<2;i++){
                int idx = tid + i*256;
                int r = idx >> 2, c = idx & 3;
                int kk = k0 + c*8;
                const __nv_bfloat16* src = (p ? Bbl : Bbh) + (size_t)(bn+r)*K + kk;
                cpa16(base + 40960 + p*10240 + r*80 + c*16, src);
            }
        }
    };

    auto COMPUTE = [&](int buf){
        const __nv_bfloat16* Ah_ = (const __nv_bfloat16*)(smx + buf*SSZ);
        const __nv_bfloat16* Al_ = (const __nv_bfloat16*)(smx + buf*SSZ + 20480);
        const __nv_bfloat16* Bh_ = (const __nv_bfloat16*)(smx + buf*SSZ + 40960);
        const __nv_bfloat16* Bl_ = (const __nv_bfloat16*)(smx + buf*SSZ + 51200);
#pragma unroll
        for (int ks=0; ks<2; ks++){
            wmma::fragment<wmma::matrix_b,16,16,16,__nv_bfloat16,wmma::col_major> fbh[4], fbl[4];
#pragma unroll
            for (int j=0;j<4;j++){
                wmma::load_matrix_sync(fbh[j], Bh_ + (wn*64+j*16)*LDAB + ks*16, LDAB);
                wmma::load_matrix_sync(fbl[j], Bl_ + (wn*64+j*16)*LDAB + ks*16, LDAB);
            }
#pragma unroll
            for (int i=0;i<4;i++){
                wmma::fragment<wmma::matrix_a,16,16,16,__nv_bfloat16,wmma::row_major> fah, fal;
                wmma::load_matrix_sync(fah, Ah_ + (wm*64+i*16)*LDAB + ks*16, LDAB);
                wmma::load_matrix_sync(fal, Al_ + (wm*64+i*16)*LDAB + ks*16, LDAB);
#pragma unroll
                for (int j=0;j<4;j++){
                    wmma::mma_sync(acc[i][j], fah, fbh[j], acc[i][j]);
                    wmma::mma_sync(acc[i][j], fah, fbl[j], acc[i][j]);
                    wmma::mma_sync(acc[i][j], fal, fbh[j], acc[i][j]);
                }
            }
        }
    };

    ISSUE(0,0); CP_COMMIT();
    ISSUE(1,1); CP_COMMIT();

    for (int kt=0; kt<KT; kt++){
        if (kt < KT-1) asm volatile("cp.async.wait_group 1;" ::: "memory");
        else           asm volatile("cp.async.wait_group 0;" ::: "memory");
        __syncthreads();
        if (kt+2 < KT){ ISSUE(kt+2, (kt+2)%3); CP_COMMIT(); }
        COMPUTE(kt % 3);
    }
    __syncthreads();

    // ---------------- epilogue via smem stage ----------------
    float* stage = (float*)smx;
#pragma unroll
    for (int i=0;i<4;i++)
#pragma unroll
        for (int j=0;j<4;j++){
            if (!TRANSC)
                wmma::store_matrix_sync(stage + (wm*64+i*16)*LDST + wn*64 + j*16,
                                        acc[i][j], LDST, wmma::mem_row_major);
            else
                wmma::store_matrix_sync(stage + (wn*64+j*16)*LDST_T + wm*64 + i*16,
                                        acc[i][j], LDST_T, wmma::mem_col_major);
        }
    __syncthreads();

    if (!TRANSC){
#pragma unroll
        for (int i=0;i<32;i++){
            int r  = wid*32 + i;
            int gm = bm + r;
            size_t grow = (size_t)z * M_batch + gm;
            float scale = 1.f;
            if (EPI==E_ELU1 || EPI==E_MASK) scale = rs[grow];
            float4 v = *(const float4*)(stage + r*LDST + lane*4);
            float o[4] = {v.x, v.y, v.z, v.w};
#pragma unroll
            for (int c=0;c<4;c++){
                float xx = o[c];
                if      (EPI==E_ELU1) xx = (xx > 0.f ? xx + 1.f : expf(xx)) * scale;
                else if (EPI==E_MASK) xx = xx * scale;
                else if (EPI==E_RELU) xx = fmaxf(xx, 0.f);
                o[c] = xx;
            }
            size_t coff = (size_t)z*c_bs + (size_t)gm*nld + bn + lane*4;
            if (OF32){
                float4 w = {o[0],o[1],o[2],o[3]};
                *(float4*)(Cf + coff) = w;
            }
            if (OBF){
                __nv_bfloat16 h[4], l[4];
#pragma unroll
                for (int c=0;c<4;c++) hilo(o[c], h[c], l[c]);
                *(__nv_bfloat162*)(Ch + coff)     = __nv_bfloat162(h[0],h[1]);
                *(__nv_bfloat162*)(Ch + coff + 2) = __nv_bfloat162(h[2],h[3]);
                *(__nv_bfloat162*)(Cl + coff)     = __nv_bfloat162(l[0],l[1]);
                *(__nv_bfloat162*)(Cl + coff + 2) = __nv_bfloat162(l[2],l[3]);
            }
        }
    } else {
        // transposed per-batch store: CT[n][col][s]; batch n fixed per tile
        const int s0 = bm & (LL-1);
        const int n  = bm >> 10;
#pragma unroll
        for (int cc=0; cc<16; cc++){
            int c = wid*16 + cc;
#pragma unroll
            for (int seg=0; seg<2; seg++){
                int rr = seg*128 + lane*4;
                float4 v = *(const float4*)(stage + c*LDST_T + rr);
                float o[4] = {v.x, v.y, v.z, v.w};
                if (EPI==E_ELU1 || EPI==E_MASK){
                    float4 sc = *(const float4*)(rs + bm + rr);
                    float s[4] = {sc.x, sc.y, sc.z, sc.w};
#pragma unroll
                    for (int ct=0;ct<4;ct++){
                        float xx = o[ct];
                        if (EPI==E_ELU1) xx = (xx > 0.f ? xx + 1.f : expf(xx)) * s[ct];
                        else             xx = xx * s[ct];
                        o[ct] = xx;
                    }
                }
                size_t coff = (size_t)n*DM*LL + (size_t)(bn + c)*LL + s0 + rr;
                __nv_bfloat16 h[4], l[4];
#pragma unroll
                for (int ct=0;ct<4;ct++) hilo(o[ct], h[ct], l[ct]);
                *(__nv_bfloat162*)(Ch + coff)     = __nv_bfloat162(h[0],h[1]);
                *(__nv_bfloat162*)(Ch + coff + 2) = __nv_bfloat162(h[2],h[3]);
                *(__nv_bfloat162*)(Cl + coff)     = __nv_bfloat162(l[0],l[1]);
                *(__nv_bfloat162*)(Cl + coff + 2) = __nv_bfloat162(l[2],l[3]);
            }
        }
    }
}

// ---------------- fp32 -> bf16 hi/lo converter ----------------------------
__global__ void cvt_hilo(const float* __restrict__ in,
                         __nv_bfloat16* __restrict__ hi,
                         __nv_bfloat16* __restrict__ lo, int n4)
{
    int i = blockIdx.x*blockDim.x + threadIdx.x;
    if (i >= n4) return;
    float4 v = ((const float4*)in)[i];
    __nv_bfloat16 h[4], l[4];
    hilo(v.x,h[0],l[0]); hilo(v.y,h[1],l[1]); hilo(v.z,h[2],l[2]); hilo(v.w,h[3],l[3]);
    ((__nv_bfloat162*)hi)[2*i]   = __nv_bfloat162(h[0],h[1]);
    ((__nv_bfloat162*)hi)[2*i+1] = __nv_bfloat162(h[2],h[3]);
    ((__nv_bfloat162*)lo)[2*i]   = __nv_bfloat162(l[0],l[1]);
    ((__nv_bfloat162*)lo)[2*i+1] = __nv_bfloat162(l[2],l[3]);
}

// ---------------- Ksum: Ks[n*512+d] = sum_s KfT[n][d][s] ------------------
__global__ void ksumT_kernel(const __nv_bfloat16* __restrict__ h,
                             const __nv_bfloat16* __restrict__ l,
                             float* __restrict__ Ks)
{
    int wid = threadIdx.x >> 5, lane = threadIdx.x & 31;
    int row = blockIdx.x * 8 + wid;
    const __nv_bfloat162* ph = (const __nv_bfloat162*)(h + (size_t)row * LL);
    const __nv_bfloat162* pl = (const __nv_bfloat162*)(l + (size_t)row * LL);
    float s = 0.f;
#pragma unroll
    for (int i = 0; i < 16; i++){
        __nv_bfloat162 a = ph[lane + i*32], b = pl[lane + i*32];
        s += __bfloat162float(a.x)+__bfloat162float(a.y)
           + __bfloat162float(b.x)+__bfloat162float(b.y);
    }
#pragma unroll
    for (int o = 16; o; o >>= 1) s += __shfl_xor_sync(0xffffffffu, s, o);
    if (!lane) Ks[row] = s;
}

// ---------------- Z: Z[r] = 1/(dot(Q[r], Ksum[n]) + 1e-6) -----------------
__global__ void z_kernel(const __nv_bfloat16* __restrict__ Qh,
                         const __nv_bfloat16* __restrict__ Ql,
                         const float* __restrict__ Ks, float* __restrict__ Z)
{
    int gw   = (blockIdx.x*blockDim.x + threadIdx.x) >> 5;
    int lane = threadIdx.x & 31;
    if (gw >= ROWS) return;
    int n = gw >> 10;
    const __nv_bfloat16* qh = Qh + (size_t)gw*DM;
    const __nv_bfloat16* ql = Ql + (size_t)gw*DM;
    const float* k = Ks + n*DM;
    float s = 0.f;
#pragma unroll
    for (int i = 0; i < DM/32; i++){
        int d = lane + i*32;
        float q = __bfloat162float(qh[d]) + __bfloat162float(ql[d]);
        s = fmaf(q, k[d], s);
    }
#pragma unroll
    for (int off = 16; off; off >>= 1) s += __shfl_xor_sync(0xffffffffu, s, off);
    if (lane == 0) Z[gw] = 1.f / (s + 1e-6f);
}

// ------- LayerNorm of (z[row] * in[row,:]) -> bf16 hi/lo out ---------------
__global__ void ln_kernel_bf(const float* __restrict__ in,
                             const float* __restrict__ Z,
                             const float* __restrict__ g, const float* __restrict__ b,
                             __nv_bfloat16* __restrict__ oh, __nv_bfloat16* __restrict__ ol)
{
    int row = blockIdx.x;
    int tid = threadIdx.x;
    float zr = Z[row];
    float4 v = *(const float4*)(in + (size_t)row*DM + tid*4);
    v.x *= zr; v.y *= zr; v.z *= zr; v.w *= zr;
    __shared__ float red[128];
    red[tid] = v.x + v.y + v.z + v.w;
    __syncthreads();
    for (int off = 64; off; off >>= 1) { if (tid < off) red[tid] += red[tid+off]; __syncthreads(); }
    float mu = red[0] * (1.f/DM);
    __syncthreads();
    float dx = v.x-mu, dy = v.y-mu, dz = v.z-mu, dw = v.w-mu;
    red[tid] = dx*dx + dy*dy + dz*dz + dw*dw;
    __syncthreads();
    for (int off = 64; off; off >>= 1) { if (tid < off) red[tid] += red[tid+off]; __syncthreads(); }
    float rstd = rsqrtf(red[0] * (1.f/DM) + 1e-5f);
    float4 gv = *(const float4*)(g + tid*4);
    float4 bv = *(const float4*)(b + tid*4);
    float o0 = dx*rstd*gv.x + bv.x, o1 = dy*rstd*gv.y + bv.y;
    float o2 = dz*rstd*gv.z + bv.z, o3 = dw*rstd*gv.w + bv.w;
    __nv_bfloat16 h[4], l[4];
    hilo(o0,h[0],l[0]); hilo(o1,h[1],l[1]); hilo(o2,h[2],l[2]); hilo(o3,h[3],l[3]);
    size_t off4 = (size_t)row*DM + tid*4;
    *(__nv_bfloat162*)(oh + off4)     = __nv_bfloat162(h[0],h[1]);
    *(__nv_bfloat162*)(oh + off4 + 2) = __nv_bfloat162(h[2],h[3]);
    *(__nv_bfloat162*)(ol + off4)     = __nv_bfloat162(l[0],l[1]);
    *(__nv_bfloat162*)(ol + off4 + 2) = __nv_bfloat162(l[2],l[3]);
}

// ---------------- out = x + LN(h2) (all fp32) ------------------------------
__global__ void ln_res_kernel(const float* __restrict__ in,
                              const float* __restrict__ x,
                              const float* __restrict__ g, const float* __restrict__ b,
                              float* __restrict__ out)
{
    int row = blockIdx.x;
    int tid = threadIdx.x;
    float4 v = *(const float4*)(in + (size_t)row*DM + tid*4);
    __shared__ float red[128];
    red[tid] = v.x + v.y + v.z + v.w;
    __syncthreads();
    for (int off = 64; off; off >>= 1) { if (tid < off) red[tid] += red[tid+off]; __syncthreads(); }
    float mu = red[0] * (1.f/DM);
    __syncthreads();
    float dx = v.x-mu, dy = v.y-mu, dz = v.z-mu, dw = v.w-mu;
    red[tid] = dx*dx + dy*dy + dz*dz + dw*dw;
    __syncthreads();
    for (int off = 64; off; off >>= 1) { if (tid < off) red[tid] += red[tid+off]; __syncthreads(); }
    float rstd = rsqrtf(red[0] * (1.f/DM) + 1e-5f);
    float4 gv = *(const float4*)(g + tid*4);
    float4 bv = *(const float4*)(b + tid*4);
    float4 xv = *(const float4*)(x + (size_t)row*DM + tid*4);
    float4 o;
    o.x = xv.x + dx*rstd*gv.x + bv.x; o.y = xv.y + dy*rstd*gv.y + bv.y;
    o.z = xv.z + dz*rstd*gv.z + bv.z; o.w = xv.w + dw*rstd*gv.w + bv.w;
    *(float4*)(out + (size_t)row*DM + tid*4) = o;
}

// =====================================================================
extern "C" void kernel_launch(void* const* d_in, const int* in_sizes, int n_in,
                              void* d_out, int out_size)
{
    const float* x   = (const float*)d_in[0];
    const float* src = (const float*)d_in[1];
    const float* Wq  = (const float*)d_in[2];
    const float* Wk  = (const float*)d_in[3];
    const float* Wv  = (const float*)d_in[4];
    const float* Wm  = (const float*)d_in[5];
    const float* W1  = (const float*)d_in[6];
    const float* W2  = (const float*)d_in[7];
    const float* g1  = (const float*)d_in[8];
    const float* b1  = (const float*)d_in[9];
    const float* g2  = (const float*)d_in[10];
    const float* b2  = (const float*)d_in[11];
    const float* xm  = (const float*)d_in[12];
    const float* sm_ = (const float*)d_in[13];
    float* out = (float*)d_out;

    __nv_bfloat16 *xh,*xl,*sh,*sl,*Wqh,*Wql,*Wkh,*Wkl,*Wvh,*Wvl,*Wmh,*Wml,*W1h,*W1l,*W2h,*W2l;
    __nv_bfloat16 *Qh,*Ql,*KfTh,*KfTl,*VfTh,*VfTl,*KVh,*KVl,*Mh,*Ml,*m2h,*m2l,*th,*tl;
    float *msg2f,*h2f,*Ks,*Zb;
    cudaGetSymbolAddress((void**)&xh, g_xh);   cudaGetSymbolAddress((void**)&xl, g_xl);
    cudaGetSymbolAddress((void**)&sh, g_sh);   cudaGetSymbolAddress((void**)&sl, g_sl);
    cudaGetSymbolAddress((void**)&Wqh,g_Wqh);  cudaGetSymbolAddress((void**)&Wql,g_Wql);
    cudaGetSymbolAddress((void**)&Wkh,g_Wkh);  cudaGetSymbolAddress((void**)&Wkl,g_Wkl);
    cudaGetSymbolAddress((void**)&Wvh,g_Wvh);  cudaGetSymbolAddress((void**)&Wvl,g_Wvl);
    cudaGetSymbolAddress((void**)&Wmh,g_Wmh);  cudaGetSymbolAddress((void**)&Wml,g_Wml);
    cudaGetSymbolAddress((void**)&W1h,g_W1h);  cudaGetSymbolAddress((void**)&W1l,g_W1l);
    cudaGetSymbolAddress((void**)&W2h,g_W2h);  cudaGetSymbolAddress((void**)&W2l,g_W2l);
    cudaGetSymbolAddress((void**)&Qh, g_Qh);   cudaGetSymbolAddress((void**)&Ql, g_Ql);
    cudaGetSymbolAddress((void**)&KfTh,g_KfTh);cudaGetSymbolAddress((void**)&KfTl,g_KfTl);
    cudaGetSymbolAddress((void**)&VfTh,g_VfTh);cudaGetSymbolAddress((void**)&VfTl,g_VfTl);
    cudaGetSymbolAddress((void**)&KVh, g_KVh); cudaGetSymbolAddress((void**)&KVl, g_KVl);
    cudaGetSymbolAddress((void**)&Mh,  g_Mh);  cudaGetSymbolAddress((void**)&Ml,  g_Ml);
    cudaGetSymbolAddress((void**)&m2h, g_m2h); cudaGetSymbolAddress((void**)&m2l, g_m2l);
    cudaGetSymbolAddress((void**)&th,  g_th);  cudaGetSymbolAddress((void**)&tl,  g_tl);
    cudaGetSymbolAddress((void**)&msg2f,g_msg2f);
    cudaGetSymbolAddress((void**)&h2f, g_h2f);
    cudaGetSymbolAddress((void**)&Ks,  g_Ksum);
    cudaGetSymbolAddress((void**)&Zb,  g_Z);

    cudaFuncSetAttribute((const void*)gemm_tc<E_ELU1,false,false,true ,false>, cudaFuncAttributeMaxDynamicSharedMemorySize, SMEM_BYTES);
    cudaFuncSetAttribute((const void*)gemm_tc<E_ELU1,true ,false,true ,false>, cudaFuncAttributeMaxDynamicSharedMemorySize, SMEM_BYTES);
    cudaFuncSetAttribute((const void*)gemm_tc<E_MASK,true ,false,true ,false>, cudaFuncAttributeMaxDynamicSharedMemorySize, SMEM_BYTES);
    cudaFuncSetAttribute((const void*)gemm_tc<E_NONE,false,false,true ,false>, cudaFuncAttributeMaxDynamicSharedMemorySize, SMEM_BYTES);
    cudaFuncSetAttribute((const void*)gemm_tc<E_NONE,false,false,false,true >, cudaFuncAttributeMaxDynamicSharedMemorySize, SMEM_BYTES);
    cudaFuncSetAttribute((const void*)gemm_tc<E_RELU,false,true ,true ,false>, cudaFuncAttributeMaxDynamicSharedMemorySize, SMEM_BYTES);

    // ---- preconvert inputs & weights to bf16 hi/lo ----
    cvt_hilo<<<(ROWS*DM/4+255)/256,256>>>(x,   xh,  xl,  ROWS*DM/4);
    cvt_hilo<<<(ROWS*DM/4+255)/256,256>>>(src, sh,  sl,  ROWS*DM/4);
    cvt_hilo<<<(DM*DM/4+255)/256,  256>>>(Wq,  Wqh, Wql, DM*DM/4);
    cvt_hilo<<<(DM*DM/4+255)/256,  256>>>(Wk,  Wkh, Wkl, DM*DM/4);
    cvt_hilo<<<(DM*DM/4+255)/256,  256>>>(Wv,  Wvh, Wvl, DM*DM/4);
    cvt_hilo<<<(DM*DM/4+255)/256,  256>>>(Wm,  Wmh, Wml, DM*DM/4);
    cvt_hilo<<<(4*DM*DM/4+255)/256,256>>>(W1,  W1h, W1l, 4*DM*DM/4);
    cvt_hilo<<<(2*DM*DM/4+255)/256,256>>>(W2,  W2h, W2l, 2*DM*DM/4);

    dim3 blk(256);

    // 1) Q = (elu(x@Wq^T)+1)*x_mask              -> hi/lo [65536,512]
    gemm_tc<E_ELU1,false,false,true,false><<<dim3(4,256,1), blk, SMEM_BYTES>>>(
        xh, xl, nullptr, nullptr, Wqh, Wql, Qh, Ql, nullptr, xm,
        DM, ROWS, 0, 0, 0, DM);
    // 2) KfT = ((elu(src@Wk^T)+1)*mask)^T        -> hi/lo [64][512][1024]
    gemm_tc<E_ELU1,true,false,true,false><<<dim3(4,256,1), blk, SMEM_BYTES>>>(
        sh, sl, nullptr, nullptr, Wkh, Wkl, KfTh, KfTl, nullptr, sm_,
        DM, ROWS, 0, 0, 0, DM);
    // 3) VfT = ((src@Wv^T)*mask)^T               -> hi/lo [64][512][1024]
    gemm_tc<E_MASK,true,false,true,false><<<dim3(4,256,1), blk, SMEM_BYTES>>>(
        sh, sl, nullptr, nullptr, Wvh, Wvl, VfTh, VfTl, nullptr, sm_,
        DM, ROWS, 0, 0, 0, DM);

    // 4) Ksum, Z  (restored: LN eps is NOT scale-invariant)
    ksumT_kernel<<<(NB*DM)/8, 256>>>(KfTh, KfTl, Ks);
    z_kernel<<<(ROWS*32)/256, 256>>>(Qh, Ql, Ks, Zb);

    // 5) KV[n][d][v] = KfT[n] @ VfT[n]^T (K=1024) -> hi/lo [64][512][512]
    gemm_tc<E_NONE,false,false,true,false><<<dim3(4,2,NB), blk, SMEM_BYTES>>>(
        KfTh, KfTl, nullptr, nullptr, VfTh, VfTl, KVh, KVl, nullptr, nullptr,
        LL, DM, (long long)DM*LL, (long long)DM*LL, (long long)DM*DM, DM);
    // 6) M[n][o][d] = Wm @ KV[n]^T (Wm folded into KV; K=512)
    gemm_tc<E_NONE,false,false,true,false><<<dim3(4,2,NB), blk, SMEM_BYTES>>>(
        Wmh, Wml, nullptr, nullptr, KVh, KVl, Mh, Ml, nullptr, nullptr,
        DM, DM, 0, (long long)DM*DM, (long long)DM*DM, DM);
    // 7) msg2 = Q[n] @ M[n]^T (unscaled; Z applied inside LN1)
    gemm_tc<E_NONE,false,false,false,true><<<dim3(4,4,NB), blk, SMEM_BYTES>>>(
        Qh, Ql, nullptr, nullptr, Mh, Ml, nullptr, nullptr, msg2f, nullptr,
        DM, LL, (long long)LL*DM, (long long)DM*DM, (long long)LL*DM, DM);

    // 8) LN1( z * msg2 ) -> bf16 hi/lo
    ln_kernel_bf<<<ROWS, 128>>>(msg2f, Zb, g1, b1, m2h, m2l);
    // 9) t = relu([x|msg2] @ W1^T)                -> hi/lo [65536,1024]
    gemm_tc<E_RELU,false,true,true,false><<<dim3(8,256,1), blk, SMEM_BYTES>>>(
        xh, xl, m2h, m2l, W1h, W1l, th, tl, nullptr, nullptr,
        2*DM, ROWS, 0, 0, 0, 2*DM);
    // 10) h2 = t @ W2^T                           -> fp32 [65536,512]
    gemm_tc<E_NONE,false,false,false,true><<<dim3(4,256,1), blk, SMEM_BYTES>>>(
        th, tl, nullptr, nullptr, W2h, W2l, nullptr, nullptr, h2f, nullptr,
        2*DM, ROWS, 0, 0, 0, DM);
    // 11) out = x + LN2(h2)
    ln_res_kernel<<<ROWS, 128>>>(h2f, x, g2, b2, out);
}

// round 11
// speedup vs baseline: 1.0000x; 1.0000x over previous
#include <cuda_runtime.h>
#include <cuda_bf16.h>
#include <mma.h>
#include <math.h>
#include <stdint.h>

using namespace nvcuda;

#define NB   64
#define LL   1024
#define DM   512
#define ROWS (NB*LL)          // 65536

// ---------------- persistent bf16 hi/lo planes + fp32 scratch -------------
__device__ __nv_bfloat16 g_xh [(size_t)ROWS*DM],  g_xl [(size_t)ROWS*DM];
__device__ __nv_bfloat16 g_sh [(size_t)ROWS*DM],  g_sl [(size_t)ROWS*DM];
__device__ __nv_bfloat16 g_Wqh[DM*DM], g_Wql[DM*DM];
__device__ __nv_bfloat16 g_Wkh[DM*DM], g_Wkl[DM*DM];
__device__ __nv_bfloat16 g_Wvh[DM*DM], g_Wvl[DM*DM];
__device__ __nv_bfloat16 g_Wmh[DM*DM], g_Wml[DM*DM];
__device__ __nv_bfloat16 g_W1h[4*DM*DM], g_W1l[4*DM*DM];
__device__ __nv_bfloat16 g_W2h[2*DM*DM], g_W2l[2*DM*DM];
__device__ __nv_bfloat16 g_Qh  [(size_t)ROWS*DM], g_Ql  [(size_t)ROWS*DM];
__device__ __nv_bfloat16 g_KfTh[(size_t)ROWS*DM], g_KfTl[(size_t)ROWS*DM];
__device__ __nv_bfloat16 g_VfTh[(size_t)ROWS*DM], g_VfTl[(size_t)ROWS*DM];
__device__ __nv_bfloat16 g_KVh [(size_t)NB*DM*DM], g_KVl [(size_t)NB*DM*DM];
__device__ __nv_bfloat16 g_Mh  [(size_t)NB*DM*DM], g_Ml  [(size_t)NB*DM*DM];
__device__ __nv_bfloat16 g_m2h [(size_t)ROWS*DM], g_m2l [(size_t)ROWS*DM];
__device__ __nv_bfloat16 g_th  [(size_t)ROWS*2*DM], g_tl [(size_t)ROWS*2*DM];
__device__ float g_msg2f[(size_t)ROWS*DM];
__device__ float g_h2f  [(size_t)ROWS*DM];
__device__ float g_Ksum [NB*DM];
__device__ float g_Z    [ROWS];

enum { E_NONE=0, E_ELU1=1, E_MASK=2, E_RELU=4 };

// smem: 3 stages; each stage = Ahi(20480) Alo(20480) Bhi(10240) Blo(10240)
#define BK    32
#define LDAB  40
#define SSZ   61440
#define SMEM_BYTES 184320
#define LDST  132
#define LDST_T 264

__device__ __forceinline__ void cpa16(uint32_t dst, const void* src){
    asm volatile("cp.async.cg.shared.global [%0], [%1], 16;" :: "r"(dst), "l"(src) : "memory");
}
#define CP_COMMIT() asm volatile("cp.async.commit_group;" ::: "memory")

__device__ __forceinline__ void hilo(float x, __nv_bfloat16& h, __nv_bfloat16& l){
    h = __float2bfloat16_rn(x);
    l = __float2bfloat16_rn(x - __bfloat162float(h));
}

// =====================================================================
// bf16 3-term split NT GEMM (cp.async 3-stage): C = A @ B^T, K-major
// CTA tile 256x128, BK=32, 256 thr / 8 warps, warp tile 64x64
// =====================================================================
template<int EPI, bool TRANSC, bool CAT, bool OBF, bool OF32>
__global__ void __launch_bounds__(256)
gemm_tc(const __nv_bfloat16* __restrict__ A1h, const __nv_bfloat16* __restrict__ A1l,
        const __nv_bfloat16* __restrict__ A2h, const __nv_bfloat16* __restrict__ A2l,
        const __nv_bfloat16* __restrict__ Bh,  const __nv_bfloat16* __restrict__ Bl,
        __nv_bfloat16* __restrict__ Ch, __nv_bfloat16* __restrict__ Cl,
        float* __restrict__ Cf, const float* __restrict__ rs,
        int K, int M_batch, long long a_bs, long long b_bs, long long c_bs, int nld)
{
    extern __shared__ char smx[];
    const uint32_t sb = (uint32_t)__cvta_generic_to_shared(smx);
    const int tid  = threadIdx.x;
    const int wid  = tid >> 5;
    const int lane = tid & 31;
    const int wm   = wid & 3;          // 64-row block
    const int wn   = wid >> 2;         // 64-col block
    const int bm   = blockIdx.y * 256;
    const int bn   = blockIdx.x * 128;
    const int z    = blockIdx.z;
    const __nv_bfloat16* Abh = A1h + (size_t)z * a_bs;
    const __nv_bfloat16* Abl = A1l + (size_t)z * a_bs;
    const __nv_bfloat16* Bbh = Bh  + (size_t)z * b_bs;
    const __nv_bfloat16* Bbl = Bl  + (size_t)z * b_bs;

    wmma::fragment<wmma::accumulator,16,16,16,float> acc[4][4];
#pragma unroll
    for (int i=0;i<4;i++)
#pragma unroll
        for (int j=0;j<4;j++) wmma::fill_fragment(acc[i][j], 0.f);

    const int KT = K / BK;

    auto ISSUE = [&](int kt, int buf){
        const int k0 = kt * BK;
        const uint32_t base = sb + buf * SSZ;
#pragma unroll
        for (int p=0;p<2;p++){
#pragma unroll
            for (int i=0;i<4;i++){
                int idx = tid + i*256;
                int r = idx >> 2, c = idx & 3;
                int kk = k0 + c*8;
                const __nv_bfloat16* src;
                if (CAT){
                    const __nv_bfloat16* bp = (kk < DM) ? (p ? A1l : A1h)
                                                        : (p ? A2l : A2h);
                    int kkk = (kk < DM) ? kk : kk - DM;
                    src = bp + (size_t)(bm+r)*DM + kkk;
                } else {
                    src = (p ? Abl : Abh) + (size_t)(bm+r)*K + kk;
                }
                cpa16(base + p*20480 + r*80 + c*16, src);
            }
        }
#pragma unroll
        for (int p=0;p<2;p++){
#pragma unroll
            for (int i=0;i<2;i++){
                int idx = tid + i*256;
                int r = idx >> 2, c = idx & 3;
                int kk = k0 + c*8;
                const __nv_bfloat16* src = (p ? Bbl : Bbh) + (size_t)(bn+r)*K + kk;
                cpa16(base + 40960 + p*10240 + r*80 + c*16, src);
            }
        }
    };

    auto COMPUTE = [&](int buf){
        const __nv_bfloat16* Ah_ = (const __nv_bfloat16*)(smx + buf*SSZ);
        const __nv_bfloat16* Al_ = (const __nv_bfloat16*)(smx + buf*SSZ + 20480);
        const __nv_bfloat16* Bh_ = (const __nv_bfloat16*)(smx + buf*SSZ + 40960);
        const __nv_bfloat16* Bl_ = (const __nv_bfloat16*)(smx + buf*SSZ + 51200);
#pragma unroll
        for (int ks=0; ks<2; ks++){
            wmma::fragment<wmma::matrix_b,16,16,16,__nv_bfloat16,wmma::col_major> fbh[4], fbl[4];
#pragma unroll
            for (int j=0;j<4;j++){
                wmma::load_matrix_sync(fbh[j], Bh_ + (wn*64+j*16)*LDAB + ks*16, LDAB);
                wmma::load_matrix_sync(fbl[j], Bl_ + (wn*64+j*16)*LDAB + ks*16, LDAB);
            }
#pragma unroll
            for (int i=0;i<4;i++){
                wmma::fragment<wmma::matrix_a,16,16,16,__nv_bfloat16,wmma::row_major> fah, fal;
                wmma::load_matrix_sync(fah, Ah_ + (wm*64+i*16)*LDAB + ks*16, LDAB);
                wmma::load_matrix_sync(fal, Al_ + (wm*64+i*16)*LDAB + ks*16, LDAB);
#pragma unroll
                for (int j=0;j<4;j++){
                    wmma::mma_sync(acc[i][j], fah, fbh[j], acc[i][j]);
                    wmma::mma_sync(acc[i][j], fah, fbl[j], acc[i][j]);
                    wmma::mma_sync(acc[i][j], fal, fbh[j], acc[i][j]);
                }
            }
        }
    };

    ISSUE(0,0); CP_COMMIT();
    ISSUE(1,1); CP_COMMIT();

    for (int kt=0; kt<KT; kt++){
        if (kt < KT-1) asm volatile("cp.async.wait_group 1;" ::: "memory");
        else           asm volatile("cp.async.wait_group 0;" ::: "memory");
        __syncthreads();
        if (kt+2 < KT){ ISSUE(kt+2, (kt+2)%3); CP_COMMIT(); }
        COMPUTE(kt % 3);
    }
    __syncthreads();

    // ---------------- epilogue via smem stage ----------------
    float* stage = (float*)smx;
#pragma unroll
    for (int i=0;i<4;i++)
#pragma unroll
        for (int j=0;j<4;j++){
            if (!TRANSC)
                wmma::store_matrix_sync(stage + (wm*64+i*16)*LDST + wn*64 + j*16,
                                        acc[i][j], LDST, wmma::mem_row_major);
            else
                wmma::store_matrix_sync(stage + (wn*64+j*16)*LDST_T + wm*64 + i*16,
                                        acc[i][j], LDST_T, wmma::mem_col_major);
        }
    __syncthreads();

    if (!TRANSC){
#pragma unroll
        for (int i=0;i<32;i++){
            int r  = wid*32 + i;
            int gm = bm + r;
            size_t grow = (size_t)z * M_batch + gm;
            float scale = 1.f;
            if (EPI==E_ELU1 || EPI==E_MASK) scale = rs[grow];
            float4 v = *(const float4*)(stage + r*LDST + lane*4);
            float o[4] = {v.x, v.y, v.z, v.w};
#pragma unroll
            for (int c=0;c<4;c++){
                float xx = o[c];
                if      (EPI==E_ELU1) xx = (xx > 0.f ? xx + 1.f : expf(xx)) * scale;
                else if (EPI==E_MASK) xx = xx * scale;
                else if (EPI==E_RELU) xx = fmaxf(xx, 0.f);
                o[c] = xx;
            }
            size_t coff = (size_t)z*c_bs + (size_t)gm*nld + bn + lane*4;
            if (OF32){
                float4 w = {o[0],o[1],o[2],o[3]};
                *(float4*)(Cf + coff) = w;
            }
            if (OBF){
                __nv_bfloat16 h[4], l[4];
#pragma unroll
                for (int c=0;c<4;c++) hilo(o[c], h[c], l[c]);
                *(__nv_bfloat162*)(Ch + coff)     = __nv_bfloat162(h[0],h[1]);
                *(__nv_bfloat162*)(Ch + coff + 2) = __nv_bfloat162(h[2],h[3]);
                *(__nv_bfloat162*)(Cl + coff)     = __nv_bfloat162(l[0],l[1]);
                *(__nv_bfloat162*)(Cl + coff + 2) = __nv_bfloat162(l[2],l[3]);
            }
        }
    } else {
        // transposed per-batch store: CT[n][col][s]; batch n fixed per tile
        const int s0 = bm & (LL-1);
        const int n  = bm >> 10;
#pragma unroll
        for (int cc=0; cc<16; cc++){
            int c = wid*16 + cc;
#pragma unroll
            for (int seg=0; seg<2; seg++){
                int rr = seg*128 + lane*4;
                float4 v = *(const float4*)(stage + c*LDST_T + rr);
                float o[4] = {v.x, v.y, v.z, v.w};
                if (EPI==E_ELU1 || EPI==E_MASK){
                    float4 sc = *(const float4*)(rs + bm + rr);
                    float s[4] = {sc.x, sc.y, sc.z, sc.w};
#pragma unroll
                    for (int ct=0;ct<4;ct++){
                        float xx = o[ct];
                        if (EPI==E_ELU1) xx = (xx > 0.f ? xx + 1.f : expf(xx)) * s[ct];
                        else             xx = xx * s[ct];
                        o[ct] = xx;
                    }
                }
                size_t coff = (size_t)n*DM*LL + (size_t)(bn + c)*LL + s0 + rr;
                __nv_bfloat16 h[4], l[4];
#pragma unroll
                for (int ct=0;ct<4;ct++) hilo(o[ct], h[ct], l[ct]);
                *(__nv_bfloat162*)(Ch + coff)     = __nv_bfloat162(h[0],h[1]);
                *(__nv_bfloat162*)(Ch + coff + 2) = __nv_bfloat162(h[2],h[3]);
                *(__nv_bfloat162*)(Cl + coff)     = __nv_bfloat162(l[0],l[1]);
                *(__nv_bfloat162*)(Cl + coff + 2) = __nv_bfloat162(l[2],l[3]);
            }
        }
    }
}

// ---------------- fp32 -> bf16 hi/lo converter ----------------------------
__global__ void cvt_hilo(const float* __restrict__ in,
                         __nv_bfloat16* __restrict__ hi,
                         __nv_bfloat16* __restrict__ lo, int n4)
{
    int i = blockIdx.x*blockDim.x + threadIdx.x;
    if (i >= n4) return;
    float4 v = ((const float4*)in)[i];
    __nv_bfloat16 h[4], l[4];
    hilo(v.x,h[0],l[0]); hilo(v.y,h[1],l[1]); hilo(v.z,h[2],l[2]); hilo(v.w,h[3],l[3]);
    ((__nv_bfloat162*)hi)[2*i]   = __nv_bfloat162(h[0],h[1]);
    ((__nv_bfloat162*)hi)[2*i+1] = __nv_bfloat162(h[2],h[3]);
    ((__nv_bfloat162*)lo)[2*i]   = __nv_bfloat162(l[0],l[1]);
    ((__nv_bfloat162*)lo)[2*i+1] = __nv_bfloat162(l[2],l[3]);
}

// ---------------- Ksum: Ks[n*512+d] = sum_s KfT[n][d][s] ------------------
__global__ void ksumT_kernel(const __nv_bfloat16* __restrict__ h,
                             const __nv_bfloat16* __restrict__ l,
                             float* __restrict__ Ks)
{
    int wid = threadIdx.x >> 5, lane = threadIdx.x & 31;
    int row = blockIdx.x * 8 + wid;
    const __nv_bfloat162* ph = (const __nv_bfloat162*)(h + (size_t)row * LL);
    const __nv_bfloat162* pl = (const __nv_bfloat162*)(l + (size_t)row * LL);
    float s = 0.f;
#pragma unroll
    for (int i = 0; i < 16; i++){
        __nv_bfloat162 a = ph[lane + i*32], b = pl[lane + i*32];
        s += __bfloat162float(a.x)+__bfloat162float(a.y)
           + __bfloat162float(b.x)+__bfloat162float(b.y);
    }
#pragma unroll
    for (int o = 16; o; o >>= 1) s += __shfl_xor_sync(0xffffffffu, s, o);
    if (!lane) Ks[row] = s;
}

// ---------------- Z: Z[r] = 1/(dot(Q[r], Ksum[n]) + 1e-6) -----------------
__global__ void z_kernel(const __nv_bfloat16* __restrict__ Qh,
                         const __nv_bfloat16* __restrict__ Ql,
                         const float* __restrict__ Ks, float* __restrict__ Z)
{
    int gw   = (blockIdx.x*blockDim.x + threadIdx.x) >> 5;
    int lane = threadIdx.x & 31;
    if (gw >= ROWS) return;
    int n = gw >> 10;
    const __nv_bfloat16* qh = Qh + (size_t)gw*DM;
    const __nv_bfloat16* ql = Ql + (size_t)gw*DM;
    const float* k = Ks + n*DM;
    float s = 0.f;
#pragma unroll
    for (int i = 0; i < DM/32; i++){
        int d = lane + i*32;
        float q = __bfloat162float(qh[d]) + __bfloat162float(ql[d]);
        s = fmaf(q, k[d], s);
    }
#pragma unroll
    for (int off = 16; off; off >>= 1) s += __shfl_xor_sync(0xffffffffu, s, off);
    if (lane == 0) Z[gw] = 1.f / (s + 1e-6f);
}

// ------- LayerNorm of (z[row] * in[row,:]) -> bf16 hi/lo out ---------------
__global__ void ln_kernel_bf(const float* __restrict__ in,
                             const float* __restrict__ Z,
                             const float* __restrict__ g, const float* __restrict__ b,
                             __nv_bfloat16* __restrict__ oh, __nv_bfloat16* __restrict__ ol)
{
    int row = blockIdx.x;
    int tid = threadIdx.x;
    float zr = Z[row];
    float4 v = *(const float4*)(in + (size_t)row*DM + tid*4);
    v.x *= zr; v.y *= zr; v.z *= zr; v.w *= zr;
    __shared__ float red[128];
    red[tid] = v.x + v.y + v.z + v.w;
    __syncthreads();
    for (int off = 64; off; off >>= 1) { if (tid < off) red[tid] += red[tid+off]; __syncthreads(); }
    float mu = red[0] * (1.f/DM);
    __syncthreads();
    float dx = v.x-mu, dy = v.y-mu, dz = v.z-mu, dw = v.w-mu;
    red[tid] = dx*dx + dy*dy + dz*dz + dw*dw;
    __syncthreads();
    for (int off = 64; off; off >>= 1) { if (tid < off) red[tid] += red[tid+off]; __syncthreads(); }
    float rstd = rsqrtf(red[0] * (1.f/DM) + 1e-5f);
    float4 gv = *(const float4*)(g + tid*4);
    float4 bv = *(const float4*)(b + tid*4);
    float o0 = dx*rstd*gv.x + bv.x, o1 = dy*rstd*gv.y + bv.y;
    float o2 = dz*rstd*gv.z + bv.z, o3 = dw*rstd*gv.w + bv.w;
    __nv_bfloat16 h[4], l[4];
    hilo(o0,h[0],l[0]); hilo(o1,h[1],l[1]); hilo(o2,h[2],l[2]); hilo(o3,h[3],l[3]);
    size_t off4 = (size_t)row*DM + tid*4;
    *(__nv_bfloat162*)(oh + off4)     = __nv_bfloat162(h[0],h[1]);
    *(__nv_bfloat162*)(oh + off4 + 2) = __nv_bfloat162(h[2],h[3]);
    *(__nv_bfloat162*)(ol + off4)     = __nv_bfloat162(l[0],l[1]);
    *(__nv_bfloat162*)(ol + off4 + 2) = __nv_bfloat162(l[2],l[3]);
}

// ---------------- out = x + LN(h2) (all fp32) ------------------------------
__global__ void ln_res_kernel(const float* __restrict__ in,
                              const float* __restrict__ x,
                              const float* __restrict__ g, const float* __restrict__ b,
                              float* __restrict__ out)
{
    int row = blockIdx.x;
    int tid = threadIdx.x;
    float4 v = *(const float4*)(in + (size_t)row*DM + tid*4);
    __shared__ float red[128];
    red[tid] = v.x + v.y + v.z + v.w;
    __syncthreads();
    for (int off = 64; off; off >>= 1) { if (tid < off) red[tid] += red[tid+off]; __syncthreads(); }
    float mu = red[0] * (1.f/DM);
    __syncthreads();
    float dx = v.x-mu, dy = v.y-mu, dz = v.z-mu, dw = v.w-mu;
    red[tid] = dx*dx + dy*dy + dz*dz + dw*dw;
    __syncthreads();
    for (int off = 64; off; off >>= 1) { if (tid < off) red[tid] += red[tid+off]; __syncthreads(); }
    float rstd = rsqrtf(red[0] * (1.f/DM) + 1e-5f);
    float4 gv = *(const float4*)(g + tid*4);
    float4 bv = *(const float4*)(b + tid*4);
    float4 xv = *(const float4*)(x + (size_t)row*DM + tid*4);
    float4 o;
    o.x = xv.x + dx*rstd*gv.x + bv.x; o.y = xv.y + dy*rstd*gv.y + bv.y;
    o.z = xv.z + dz*rstd*gv.z + bv.z; o.w = xv.w + dw*rstd*gv.w + bv.w;
    *(float4*)(out + (size_t)row*DM + tid*4) = o;
}

// =====================================================================
extern "C" void kernel_launch(void* const* d_in, const int* in_sizes, int n_in,
                              void* d_out, int out_size)
{
    const float* x   = (const float*)d_in[0];
    const float* src = (const float*)d_in[1];
    const float* Wq  = (const float*)d_in[2];
    const float* Wk  = (const float*)d_in[3];
    const float* Wv  = (const float*)d_in[4];
    const float* Wm  = (const float*)d_in[5];
    const float* W1  = (const float*)d_in[6];
    const float* W2  = (const float*)d_in[7];
    const float* g1  = (const float*)d_in[8];
    const float* b1  = (const float*)d_in[9];
    const float* g2  = (const float*)d_in[10];
    const float* b2  = (const float*)d_in[11];
    const float* xm  = (const float*)d_in[12];
    const float* sm_ = (const float*)d_in[13];
    float* out = (float*)d_out;

    __nv_bfloat16 *xh,*xl,*sh,*sl,*Wqh,*Wql,*Wkh,*Wkl,*Wvh,*Wvl,*Wmh,*Wml,*W1h,*W1l,*W2h,*W2l;
    __nv_bfloat16 *Qh,*Ql,*KfTh,*KfTl,*VfTh,*VfTl,*KVh,*KVl,*Mh,*Ml,*m2h,*m2l,*th,*tl;
    float *msg2f,*h2f,*Ks,*Zb;
    cudaGetSymbolAddress((void**)&xh, g_xh);   cudaGetSymbolAddress((void**)&xl, g_xl);
    cudaGetSymbolAddress((void**)&sh, g_sh);   cudaGetSymbolAddress((void**)&sl, g_sl);
    cudaGetSymbolAddress((void**)&Wqh,g_Wqh);  cudaGetSymbolAddress((void**)&Wql,g_Wql);
    cudaGetSymbolAddress((void**)&Wkh,g_Wkh);  cudaGetSymbolAddress((void**)&Wkl,g_Wkl);
    cudaGetSymbolAddress((void**)&Wvh,g_Wvh);  cudaGetSymbolAddress((void**)&Wvl,g_Wvl);
    cudaGetSymbolAddress((void**)&Wmh,g_Wmh);  cudaGetSymbolAddress((void**)&Wml,g_Wml);
    cudaGetSymbolAddress((void**)&W1h,g_W1h);  cudaGetSymbolAddress((void**)&W1l,g_W1l);
    cudaGetSymbolAddress((void**)&W2h,g_W2h);  cudaGetSymbolAddress((void**)&W2l,g_W2l);
    cudaGetSymbolAddress((void**)&Qh, g_Qh);   cudaGetSymbolAddress((void**)&Ql, g_Ql);
    cudaGetSymbolAddress((void**)&KfTh,g_KfTh);cudaGetSymbolAddress((void**)&KfTl,g_KfTl);
    cudaGetSymbolAddress((void**)&VfTh,g_VfTh);cudaGetSymbolAddress((void**)&VfTl,g_VfTl);
    cudaGetSymbolAddress((void**)&KVh, g_KVh); cudaGetSymbolAddress((void**)&KVl, g_KVl);
    cudaGetSymbolAddress((void**)&Mh,  g_Mh);  cudaGetSymbolAddress((void**)&Ml,  g_Ml);
    cudaGetSymbolAddress((void**)&m2h, g_m2h); cudaGetSymbolAddress((void**)&m2l, g_m2l);
    cudaGetSymbolAddress((void**)&th,  g_th);  cudaGetSymbolAddress((void**)&tl,  g_tl);
    cudaGetSymbolAddress((void**)&msg2f,g_msg2f);
    cudaGetSymbolAddress((void**)&h2f, g_h2f);
    cudaGetSymbolAddress((void**)&Ks,  g_Ksum);
    cudaGetSymbolAddress((void**)&Zb,  g_Z);

    cudaFuncSetAttribute((const void*)gemm_tc<E_ELU1,false,false,true ,false>, cudaFuncAttributeMaxDynamicSharedMemorySize, SMEM_BYTES);
    cudaFuncSetAttribute((const void*)gemm_tc<E_ELU1,true ,false,true ,false>, cudaFuncAttributeMaxDynamicSharedMemorySize, SMEM_BYTES);
    cudaFuncSetAttribute((const void*)gemm_tc<E_MASK,true ,false,true ,false>, cudaFuncAttributeMaxDynamicSharedMemorySize, SMEM_BYTES);
    cudaFuncSetAttribute((const void*)gemm_tc<E_NONE,false,false,true ,false>, cudaFuncAttributeMaxDynamicSharedMemorySize, SMEM_BYTES);
    cudaFuncSetAttribute((const void*)gemm_tc<E_NONE,false,false,false,true >, cudaFuncAttributeMaxDynamicSharedMemorySize, SMEM_BYTES);
    cudaFuncSetAttribute((const void*)gemm_tc<E_RELU,false,true ,true ,false>, cudaFuncAttributeMaxDynamicSharedMemorySize, SMEM_BYTES);

    // ---- preconvert inputs & weights to bf16 hi/lo ----
    cvt_hilo<<<(ROWS*DM/4+255)/256,256>>>(x,   xh,  xl,  ROWS*DM/4);
    cvt_hilo<<<(ROWS*DM/4+255)/256,256>>>(src, sh,  sl,  ROWS*DM/4);
    cvt_hilo<<<(DM*DM/4+255)/256,  256>>>(Wq,  Wqh, Wql, DM*DM/4);
    cvt_hilo<<<(DM*DM/4+255)/256,  256>>>(Wk,  Wkh, Wkl, DM*DM/4);
    cvt_hilo<<<(DM*DM/4+255)/256,  256>>>(Wv,  Wvh, Wvl, DM*DM/4);
    cvt_hilo<<<(DM*DM/4+255)/256,  256>>>(Wm,  Wmh, Wml, DM*DM/4);
    cvt_hilo<<<(4*DM*DM/4+255)/256,256>>>(W1,  W1h, W1l, 4*DM*DM/4);
    cvt_hilo<<<(2*DM*DM/4+255)/256,256>>>(W2,  W2h, W2l, 2*DM*DM/4);

    dim3 blk(256);

    // 1) Q = (elu(x@Wq^T)+1)*x_mask              -> hi/lo [65536,512]
    gemm_tc<E_ELU1,false,false,true,false><<<dim3(4,256,1), blk, SMEM_BYTES>>>(
        xh, xl, nullptr, nullptr, Wqh, Wql, Qh, Ql, nullptr, xm,
        DM, ROWS, 0, 0, 0, DM);
    // 2) KfT = ((elu(src@Wk^T)+1)*mask)^T        -> hi/lo [64][512][1024]
    gemm_tc<E_ELU1,true,false,true,false><<<dim3(4,256,1), blk, SMEM_BYTES>>>(
        sh, sl, nullptr, nullptr, Wkh, Wkl, KfTh, KfTl, nullptr, sm_,
        DM, ROWS, 0, 0, 0, DM);
    // 3) VfT = ((src@Wv^T)*mask)^T               -> hi/lo [64][512][1024]
    gemm_tc<E_MASK,true,false,true,false><<<dim3(4,256,1), blk, SMEM_BYTES>>>(
        sh, sl, nullptr, nullptr, Wvh, Wvl, VfTh, VfTl, nullptr, sm_,
        DM, ROWS, 0, 0, 0, DM);

    // 4) Ksum, Z  (restored: LN eps is NOT scale-invariant)
    ksumT_kernel<<<(NB*DM)/8, 256>>>(KfTh, KfTl, Ks);
    z_kernel<<<(ROWS*32)/256, 256>>>(Qh, Ql, Ks, Zb);

    // 5) KV[n][d][v] = KfT[n] @ VfT[n]^T (K=1024) -> hi/lo [64][512][512]
    gemm_tc<E_NONE,false,false,true,false><<<dim3(4,2,NB), blk, SMEM_BYTES>>>(
        KfTh, KfTl, nullptr, nullptr, VfTh, VfTl, KVh, KVl, nullptr, nullptr,
        LL, DM, (long long)DM*LL, (long long)DM*LL, (long long)DM*DM, DM);
    // 6) M[n][o][d] = Wm @ KV[n]^T (Wm folded into KV; K=512)
    gemm_tc<E_NONE,false,false,true,false><<<dim3(4,2,NB), blk, SMEM_BYTES>>>(
        Wmh, Wml, nullptr, nullptr, KVh, KVl, Mh, Ml, nullptr, nullptr,
        DM, DM, 0, (long long)DM*DM, (long long)DM*DM, DM);
    // 7) msg2 = Q[n] @ M[n]^T (unscaled; Z applied inside LN1)
    gemm_tc<E_NONE,false,false,false,true><<<dim3(4,4,NB), blk, SMEM_BYTES>>>(
        Qh, Ql, nullptr, nullptr, Mh, Ml, nullptr, nullptr, msg2f, nullptr,
        DM, LL, (long long)LL*DM, (long long)DM*DM, (long long)LL*DM, DM);

    // 8) LN1( z * msg2 ) -> bf16 hi/lo
    ln_kernel_bf<<<ROWS, 128>>>(msg2f, Zb, g1, b1, m2h, m2l);
    // 9) t = relu([x|msg2] @ W1^T)                -> hi/lo [65536,1024]
    gemm_tc<E_RELU,false,true,true,false><<<dim3(8,256,1), blk, SMEM_BYTES>>>(
        xh, xl, m2h, m2l, W1h, W1l, th, tl, nullptr, nullptr,
        2*DM, ROWS, 0, 0, 0, 2*DM);
    // 10) h2 = t @ W2^T                           -> fp32 [65536,512]
    gemm_tc<E_NONE,false,false,false,true><<<dim3(4,256,1), blk, SMEM_BYTES>>>(
        th, tl, nullptr, nullptr, W2h, W2l, nullptr, nullptr, h2f, nullptr,
        2*DM, ROWS, 0, 0, 0, DM);
    // 11) out = x + LN2(h2)
    ln_res_kernel<<<ROWS, 128>>>(h2f, x, g2, b2, out);
}

// round 12
// speedup vs baseline: 1.0008x; 1.0008x over previous
#include <cuda_runtime.h>
#include <cuda_bf16.h>
#include <mma.h>
#include <math.h>
#include <stdint.h>

using namespace nvcuda;

#define NB   64
#define LL   1024
#define DM   512
#define ROWS (NB*LL)          // 65536

// ---------------- persistent bf16 hi/lo planes + fp32 scratch -------------
__device__ __nv_bfloat16 g_xh [(size_t)ROWS*DM],  g_xl [(size_t)ROWS*DM];
__device__ __nv_bfloat16 g_sh [(size_t)ROWS*DM],  g_sl [(size_t)ROWS*DM];
__device__ __nv_bfloat16 g_Wqh[DM*DM], g_Wql[DM*DM];
__device__ __nv_bfloat16 g_Wkh[DM*DM], g_Wkl[DM*DM];
__device__ __nv_bfloat16 g_Wvh[DM*DM], g_Wvl[DM*DM];
__device__ __nv_bfloat16 g_Wmh[DM*DM], g_Wml[DM*DM];
__device__ __nv_bfloat16 g_W1h[4*DM*DM], g_W1l[4*DM*DM];
__device__ __nv_bfloat16 g_W2h[2*DM*DM], g_W2l[2*DM*DM];
__device__ __nv_bfloat16 g_Qh  [(size_t)ROWS*DM], g_Ql  [(size_t)ROWS*DM];
__device__ __nv_bfloat16 g_KfTh[(size_t)ROWS*DM], g_KfTl[(size_t)ROWS*DM];
__device__ __nv_bfloat16 g_VfTh[(size_t)ROWS*DM], g_VfTl[(size_t)ROWS*DM];
__device__ __nv_bfloat16 g_KVh [(size_t)NB*DM*DM], g_KVl [(size_t)NB*DM*DM];
__device__ __nv_bfloat16 g_Mh  [(size_t)NB*DM*DM], g_Ml  [(size_t)NB*DM*DM];
__device__ __nv_bfloat16 g_m2h [(size_t)ROWS*DM], g_m2l [(size_t)ROWS*DM];
__device__ __nv_bfloat16 g_th  [(size_t)ROWS*2*DM], g_tl [(size_t)ROWS*2*DM];
__device__ float g_msg2f[(size_t)ROWS*DM];
__device__ float g_h2f  [(size_t)ROWS*DM];
__device__ float g_Ksum [NB*DM];
__device__ float g_Z    [ROWS];

enum { E_NONE=0, E_ELU1=1, E_MASK=2, E_RELU=4 };

// smem: 3 stages; each stage = Ahi(20480) Alo(20480) Bhi(10240) Blo(10240)
#define BK    32
#define LDAB  40
#define SSZ   61440
#define SMEM_BYTES 184320
#define LDST  132
#define LDST_T 264

__device__ __forceinline__ void cpa16(uint32_t dst, const void* src){
    asm volatile("cp.async.cg.shared.global [%0], [%1], 16;" :: "r"(dst), "l"(src) : "memory");
}
#define CP_COMMIT() asm volatile("cp.async.commit_group;" ::: "memory")

__device__ __forceinline__ void hilo(float x, __nv_bfloat16& h, __nv_bfloat16& l){
    h = __float2bfloat16_rn(x);
    l = __float2bfloat16_rn(x - __bfloat162float(h));
}

// =====================================================================
// bf16 3-term split NT GEMM (cp.async 3-stage): C = A @ B^T, K-major
// CTA tile 256x128, BK=32, 256 thr / 8 warps, warp tile 64x64
// =====================================================================
template<int EPI, bool TRANSC, bool CAT, bool OBF, bool OF32>
__global__ void __launch_bounds__(256)
gemm_tc(const __nv_bfloat16* __restrict__ A1h, const __nv_bfloat16* __restrict__ A1l,
        const __nv_bfloat16* __restrict__ A2h, const __nv_bfloat16* __restrict__ A2l,
        const __nv_bfloat16* __restrict__ Bh,  const __nv_bfloat16* __restrict__ Bl,
        __nv_bfloat16* __restrict__ Ch, __nv_bfloat16* __restrict__ Cl,
        float* __restrict__ Cf, const float* __restrict__ rs,
        int K, int M_batch, long long a_bs, long long b_bs, long long c_bs, int nld)
{
    extern __shared__ char smx[];
    const uint32_t sb = (uint32_t)__cvta_generic_to_shared(smx);
    const int tid  = threadIdx.x;
    const int wid  = tid >> 5;
    const int lane = tid & 31;
    const int wm   = wid & 3;          // 64-row block
    const int wn   = wid >> 2;         // 64-col block
    const int bm   = blockIdx.y * 256;
    const int bn   = blockIdx.x * 128;
    const int z    = blockIdx.z;
    const __nv_bfloat16* Abh = A1h + (size_t)z * a_bs;
    const __nv_bfloat16* Abl = A1l + (size_t)z * a_bs;
    const __nv_bfloat16* Bbh = Bh  + (size_t)z * b_bs;
    const __nv_bfloat16* Bbl = Bl  + (size_t)z * b_bs;

    wmma::fragment<wmma::accumulator,16,16,16,float> acc[4][4];
#pragma unroll
    for (int i=0;i<4;i++)
#pragma unroll
        for (int j=0;j<4;j++) wmma::fill_fragment(acc[i][j], 0.f);

    const int KT = K / BK;

    auto ISSUE = [&](int kt, int buf){
        const int k0 = kt * BK;
        const uint32_t base = sb + buf * SSZ;
#pragma unroll
        for (int p=0;p<2;p++){
#pragma unroll
            for (int i=0;i<4;i++){
                int idx = tid + i*256;
                int r = idx >> 2, c = idx & 3;
                int kk = k0 + c*8;
                const __nv_bfloat16* src;
                if (CAT){
                    const __nv_bfloat16* bp = (kk < DM) ? (p ? A1l : A1h)
                                                        : (p ? A2l : A2h);
                    int kkk = (kk < DM) ? kk : kk - DM;
                    src = bp + (size_t)(bm+r)*DM + kkk;
                } else {
                    src = (p ? Abl : Abh) + (size_t)(bm+r)*K + kk;
                }
                cpa16(base + p*20480 + r*80 + c*16, src);
            }
        }
#pragma unroll
        for (int p=0;p<2;p++){
#pragma unroll
            for (int i=0;i<2;i++){
                int idx = tid + i*256;
                int r = idx >> 2, c = idx & 3;
                int kk = k0 + c*8;
                const __nv_bfloat16* src = (p ? Bbl : Bbh) + (size_t)(bn+r)*K + kk;
                cpa16(base + 40960 + p*10240 + r*80 + c*16, src);
            }
        }
    };

    auto COMPUTE = [&](int buf){
        const __nv_bfloat16* Ah_ = (const __nv_bfloat16*)(smx + buf*SSZ);
        const __nv_bfloat16* Al_ = (const __nv_bfloat16*)(smx + buf*SSZ + 20480);
        const __nv_bfloat16* Bh_ = (const __nv_bfloat16*)(smx + buf*SSZ + 40960);
        const __nv_bfloat16* Bl_ = (const __nv_bfloat16*)(smx + buf*SSZ + 51200);
#pragma unroll
        for (int ks=0; ks<2; ks++){
            wmma::fragment<wmma::matrix_b,16,16,16,__nv_bfloat16,wmma::col_major> fbh[4], fbl[4];
#pragma unroll
            for (int j=0;j<4;j++){
                wmma::load_matrix_sync(fbh[j], Bh_ + (wn*64+j*16)*LDAB + ks*16, LDAB);
                wmma::load_matrix_sync(fbl[j], Bl_ + (wn*64+j*16)*LDAB + ks*16, LDAB);
            }
#pragma unroll
            for (int i=0;i<4;i++){
                wmma::fragment<wmma::matrix_a,16,16,16,__nv_bfloat16,wmma::row_major> fah, fal;
                wmma::load_matrix_sync(fah, Ah_ + (wm*64+i*16)*LDAB + ks*16, LDAB);
                wmma::load_matrix_sync(fal, Al_ + (wm*64+i*16)*LDAB + ks*16, LDAB);
#pragma unroll
                for (int j=0;j<4;j++){
                    wmma::mma_sync(acc[i][j], fah, fbh[j], acc[i][j]);
                    wmma::mma_sync(acc[i][j], fah, fbl[j], acc[i][j]);
                    wmma::mma_sync(acc[i][j], fal, fbh[j], acc[i][j]);
                }
            }
        }
    };

    ISSUE(0,0); CP_COMMIT();
    ISSUE(1,1); CP_COMMIT();

    for (int kt=0; kt<KT; kt++){
        if (kt < KT-1) asm volatile("cp.async.wait_group 1;" ::: "memory");
        else           asm volatile("cp.async.wait_group 0;" ::: "memory");
        __syncthreads();
        if (kt+2 < KT){ ISSUE(kt+2, (kt+2)%3); CP_COMMIT(); }
        COMPUTE(kt % 3);
    }
    __syncthreads();

    // ---------------- epilogue via smem stage ----------------
    float* stage = (float*)smx;
#pragma unroll
    for (int i=0;i<4;i++)
#pragma unroll
        for (int j=0;j<4;j++){
            if (!TRANSC)
                wmma::store_matrix_sync(stage + (wm*64+i*16)*LDST + wn*64 + j*16,
                                        acc[i][j], LDST, wmma::mem_row_major);
            else
                wmma::store_matrix_sync(stage + (wn*64+j*16)*LDST_T + wm*64 + i*16,
                                        acc[i][j], LDST_T, wmma::mem_col_major);
        }
    __syncthreads();

    if (!TRANSC){
#pragma unroll
        for (int i=0;i<32;i++){
            int r  = wid*32 + i;
            int gm = bm + r;
            size_t grow = (size_t)z * M_batch + gm;
            float scale = 1.f;
            if (EPI==E_ELU1 || EPI==E_MASK) scale = rs[grow];
            float4 v = *(const float4*)(stage + r*LDST + lane*4);
            float o[4] = {v.x, v.y, v.z, v.w};
#pragma unroll
            for (int c=0;c<4;c++){
                float xx = o[c];
                if      (EPI==E_ELU1) xx = (xx > 0.f ? xx + 1.f : expf(xx)) * scale;
                else if (EPI==E_MASK) xx = xx * scale;
                else if (EPI==E_RELU) xx = fmaxf(xx, 0.f);
                o[c] = xx;
            }
            size_t coff = (size_t)z*c_bs + (size_t)gm*nld + bn + lane*4;
            if (OF32){
                float4 w = {o[0],o[1],o[2],o[3]};
                *(float4*)(Cf + coff) = w;
            }
            if (OBF){
                __nv_bfloat16 h[4], l[4];
#pragma unroll
                for (int c=0;c<4;c++) hilo(o[c], h[c], l[c]);
                *(__nv_bfloat162*)(Ch + coff)     = __nv_bfloat162(h[0],h[1]);
                *(__nv_bfloat162*)(Ch + coff + 2) = __nv_bfloat162(h[2],h[3]);
                *(__nv_bfloat162*)(Cl + coff)     = __nv_bfloat162(l[0],l[1]);
                *(__nv_bfloat162*)(Cl + coff + 2) = __nv_bfloat162(l[2],l[3]);
            }
        }
    } else {
        // transposed per-batch store: CT[n][col][s]; batch n fixed per tile
        const int s0 = bm & (LL-1);
        const int n  = bm >> 10;
#pragma unroll
        for (int cc=0; cc<16; cc++){
            int c = wid*16 + cc;
#pragma unroll
            for (int seg=0; seg<2; seg++){
                int rr = seg*128 + lane*4;
                float4 v = *(const float4*)(stage + c*LDST_T + rr);
                float o[4] = {v.x, v.y, v.z, v.w};
                if (EPI==E_ELU1 || EPI==E_MASK){
                    float4 sc = *(const float4*)(rs + bm + rr);
                    float s[4] = {sc.x, sc.y, sc.z, sc.w};
#pragma unroll
                    for (int ct=0;ct<4;ct++){
                        float xx = o[ct];
                        if (EPI==E_ELU1) xx = (xx > 0.f ? xx + 1.f : expf(xx)) * s[ct];
                        else             xx = xx * s[ct];
                        o[ct] = xx;
                    }
                }
                size_t coff = (size_t)n*DM*LL + (size_t)(bn + c)*LL + s0 + rr;
                __nv_bfloat16 h[4], l[4];
#pragma unroll
                for (int ct=0;ct<4;ct++) hilo(o[ct], h[ct], l[ct]);
                *(__nv_bfloat162*)(Ch + coff)     = __nv_bfloat162(h[0],h[1]);
                *(__nv_bfloat162*)(Ch + coff + 2) = __nv_bfloat162(h[2],h[3]);
                *(__nv_bfloat162*)(Cl + coff)     = __nv_bfloat162(l[0],l[1]);
                *(__nv_bfloat162*)(Cl + coff + 2) = __nv_bfloat162(l[2],l[3]);
            }
        }
    }
}

// ---------------- fp32 -> bf16 hi/lo converter ----------------------------
__global__ void cvt_hilo(const float* __restrict__ in,
                         __nv_bfloat16* __restrict__ hi,
                         __nv_bfloat16* __restrict__ lo, int n4)
{
    int i = blockIdx.x*blockDim.x + threadIdx.x;
    if (i >= n4) return;
    float4 v = ((const float4*)in)[i];
    __nv_bfloat16 h[4], l[4];
    hilo(v.x,h[0],l[0]); hilo(v.y,h[1],l[1]); hilo(v.z,h[2],l[2]); hilo(v.w,h[3],l[3]);
    ((__nv_bfloat162*)hi)[2*i]   = __nv_bfloat162(h[0],h[1]);
    ((__nv_bfloat162*)hi)[2*i+1] = __nv_bfloat162(h[2],h[3]);
    ((__nv_bfloat162*)lo)[2*i]   = __nv_bfloat162(l[0],l[1]);
    ((__nv_bfloat162*)lo)[2*i+1] = __nv_bfloat162(l[2],l[3]);
}

// ---------------- Ksum: Ks[n*512+d] = sum_s KfT[n][d][s] ------------------
__global__ void ksumT_kernel(const __nv_bfloat16* __restrict__ h,
                             const __nv_bfloat16* __restrict__ l,
                             float* __restrict__ Ks)
{
    int wid = threadIdx.x >> 5, lane = threadIdx.x & 31;
    int row = blockIdx.x * 8 + wid;
    const __nv_bfloat162* ph = (const __nv_bfloat162*)(h + (size_t)row * LL);
    const __nv_bfloat162* pl = (const __nv_bfloat162*)(l + (size_t)row * LL);
    float s = 0.f;
#pragma unroll
    for (int i = 0; i < 16; i++){
        __nv_bfloat162 a = ph[lane + i*32], b = pl[lane + i*32];
        s += __bfloat162float(a.x)+__bfloat162float(a.y)
           + __bfloat162float(b.x)+__bfloat162float(b.y);
    }
#pragma unroll
    for (int o = 16; o; o >>= 1) s += __shfl_xor_sync(0xffffffffu, s, o);
    if (!lane) Ks[row] = s;
}

// ---------------- Z: Z[r] = 1/(dot(Q[r], Ksum[n]) + 1e-6) -----------------
__global__ void z_kernel(const __nv_bfloat16* __restrict__ Qh,
                         const __nv_bfloat16* __restrict__ Ql,
                         const float* __restrict__ Ks, float* __restrict__ Z)
{
    int gw   = (blockIdx.x*blockDim.x + threadIdx.x) >> 5;
    int lane = threadIdx.x & 31;
    if (gw >= ROWS) return;
    int n = gw >> 10;
    const __nv_bfloat16* qh = Qh + (size_t)gw*DM;
    const __nv_bfloat16* ql = Ql + (size_t)gw*DM;
    const float* k = Ks + n*DM;
    float s = 0.f;
#pragma unroll
    for (int i = 0; i < DM/32; i++){
        int d = lane + i*32;
        float q = __bfloat162float(qh[d]) + __bfloat162float(ql[d]);
        s = fmaf(q, k[d], s);
    }
#pragma unroll
    for (int off = 16; off; off >>= 1) s += __shfl_xor_sync(0xffffffffu, s, off);
    if (lane == 0) Z[gw] = 1.f / (s + 1e-6f);
}

// ------- LayerNorm of (z[row] * in[row,:]) -> bf16 hi/lo out ---------------
__global__ void ln_kernel_bf(const float* __restrict__ in,
                             const float* __restrict__ Z,
                             const float* __restrict__ g, const float* __restrict__ b,
                             __nv_bfloat16* __restrict__ oh, __nv_bfloat16* __restrict__ ol)
{
    int row = blockIdx.x;
    int tid = threadIdx.x;
    float zr = Z[row];
    float4 v = *(const float4*)(in + (size_t)row*DM + tid*4);
    v.x *= zr; v.y *= zr; v.z *= zr; v.w *= zr;
    __shared__ float red[128];
    red[tid] = v.x + v.y + v.z + v.w;
    __syncthreads();
    for (int off = 64; off; off >>= 1) { if (tid < off) red[tid] += red[tid+off]; __syncthreads(); }
    float mu = red[0] * (1.f/DM);
    __syncthreads();
    float dx = v.x-mu, dy = v.y-mu, dz = v.z-mu, dw = v.w-mu;
    red[tid] = dx*dx + dy*dy + dz*dz + dw*dw;
    __syncthreads();
    for (int off = 64; off; off >>= 1) { if (tid < off) red[tid] += red[tid+off]; __syncthreads(); }
    float rstd = rsqrtf(red[0] * (1.f/DM) + 1e-5f);
    float4 gv = *(const float4*)(g + tid*4);
    float4 bv = *(const float4*)(b + tid*4);
    float o0 = dx*rstd*gv.x + bv.x, o1 = dy*rstd*gv.y + bv.y;
    float o2 = dz*rstd*gv.z + bv.z, o3 = dw*rstd*gv.w + bv.w;
    __nv_bfloat16 h[4], l[4];
    hilo(o0,h[0],l[0]); hilo(o1,h[1],l[1]); hilo(o2,h[2],l[2]); hilo(o3,h[3],l[3]);
    size_t off4 = (size_t)row*DM + tid*4;
    *(__nv_bfloat162*)(oh + off4)     = __nv_bfloat162(h[0],h[1]);
    *(__nv_bfloat162*)(oh + off4 + 2) = __nv_bfloat162(h[2],h[3]);
    *(__nv_bfloat162*)(ol + off4)     = __nv_bfloat162(l[0],l[1]);
    *(__nv_bfloat162*)(ol + off4 + 2) = __nv_bfloat162(l[2],l[3]);
}

// ---------------- out = x + LN(h2) (all fp32) ------------------------------
__global__ void ln_res_kernel(const float* __restrict__ in,
                              const float* __restrict__ x,
                              const float* __restrict__ g, const float* __restrict__ b,
                              float* __restrict__ out)
{
    int row = blockIdx.x;
    int tid = threadIdx.x;
    float4 v = *(const float4*)(in + (size_t)row*DM + tid*4);
    __shared__ float red[128];
    red[tid] = v.x + v.y + v.z + v.w;
    __syncthreads();
    for (int off = 64; off; off >>= 1) { if (tid < off) red[tid] += red[tid+off]; __syncthreads(); }
    float mu = red[0] * (1.f/DM);
    __syncthreads();
    float dx = v.x-mu, dy = v.y-mu, dz = v.z-mu, dw = v.w-mu;
    red[tid] = dx*dx + dy*dy + dz*dz + dw*dw;
    __syncthreads();
    for (int off = 64; off; off >>= 1) { if (tid < off) red[tid] += red[tid+off]; __syncthreads(); }
    float rstd = rsqrtf(red[0] * (1.f/DM) + 1e-5f);
    float4 gv = *(const float4*)(g + tid*4);
    float4 bv = *(const float4*)(b + tid*4);
    float4 xv = *(const float4*)(x + (size_t)row*DM + tid*4);
    float4 o;
    o.x = xv.x + dx*rstd*gv.x + bv.x; o.y = xv.y + dy*rstd*gv.y + bv.y;
    o.z = xv.z + dz*rstd*gv.z + bv.z; o.w = xv.w + dw*rstd*gv.w + bv.w;
    *(float4*)(out + (size_t)row*DM + tid*4) = o;
}

// =====================================================================
extern "C" void kernel_launch(void* const* d_in, const int* in_sizes, int n_in,
                              void* d_out, int out_size)
{
    const float* x   = (const float*)d_in[0];
    const float* src = (const float*)d_in[1];
    const float* Wq  = (const float*)d_in[2];
    const float* Wk  = (const float*)d_in[3];
    const float* Wv  = (const float*)d_in[4];
    const float* Wm  = (const float*)d_in[5];
    const float* W1  = (const float*)d_in[6];
    const float* W2  = (const float*)d_in[7];
    const float* g1  = (const float*)d_in[8];
    const float* b1  = (const float*)d_in[9];
    const float* g2  = (const float*)d_in[10];
    const float* b2  = (const float*)d_in[11];
    const float* xm  = (const float*)d_in[12];
    const float* sm_ = (const float*)d_in[13];
    float* out = (float*)d_out;

    __nv_bfloat16 *xh,*xl,*sh,*sl,*Wqh,*Wql,*Wkh,*Wkl,*Wvh,*Wvl,*Wmh,*Wml,*W1h,*W1l,*W2h,*W2l;
    __nv_bfloat16 *Qh,*Ql,*KfTh,*KfTl,*VfTh,*VfTl,*KVh,*KVl,*Mh,*Ml,*m2h,*m2l,*th,*tl;
    float *msg2f,*h2f,*Ks,*Zb;
    cudaGetSymbolAddress((void**)&xh, g_xh);   cudaGetSymbolAddress((void**)&xl, g_xl);
    cudaGetSymbolAddress((void**)&sh, g_sh);   cudaGetSymbolAddress((void**)&sl, g_sl);
    cudaGetSymbolAddress((void**)&Wqh,g_Wqh);  cudaGetSymbolAddress((void**)&Wql,g_Wql);
    cudaGetSymbolAddress((void**)&Wkh,g_Wkh);  cudaGetSymbolAddress((void**)&Wkl,g_Wkl);
    cudaGetSymbolAddress((void**)&Wvh,g_Wvh);  cudaGetSymbolAddress((void**)&Wvl,g_Wvl);
    cudaGetSymbolAddress((void**)&Wmh,g_Wmh);  cudaGetSymbolAddress((void**)&Wml,g_Wml);
    cudaGetSymbolAddress((void**)&W1h,g_W1h);  cudaGetSymbolAddress((void**)&W1l,g_W1l);
    cudaGetSymbolAddress((void**)&W2h,g_W2h);  cudaGetSymbolAddress((void**)&W2l,g_W2l);
    cudaGetSymbolAddress((void**)&Qh, g_Qh);   cudaGetSymbolAddress((void**)&Ql, g_Ql);
    cudaGetSymbolAddress((void**)&KfTh,g_KfTh);cudaGetSymbolAddress((void**)&KfTl,g_KfTl);
    cudaGetSymbolAddress((void**)&VfTh,g_VfTh);cudaGetSymbolAddress((void**)&VfTl,g_VfTl);
    cudaGetSymbolAddress((void**)&KVh, g_KVh); cudaGetSymbolAddress((void**)&KVl, g_KVl);
    cudaGetSymbolAddress((void**)&Mh,  g_Mh);  cudaGetSymbolAddress((void**)&Ml,  g_Ml);
    cudaGetSymbolAddress((void**)&m2h, g_m2h); cudaGetSymbolAddress((void**)&m2l, g_m2l);
    cudaGetSymbolAddress((void**)&th,  g_th);  cudaGetSymbolAddress((void**)&tl,  g_tl);
    cudaGetSymbolAddress((void**)&msg2f,g_msg2f);
    cudaGetSymbolAddress((void**)&h2f, g_h2f);
    cudaGetSymbolAddress((void**)&Ks,  g_Ksum);
    cudaGetSymbolAddress((void**)&Zb,  g_Z);

    cudaFuncSetAttribute((const void*)gemm_tc<E_ELU1,false,false,true ,false>, cudaFuncAttributeMaxDynamicSharedMemorySize, SMEM_BYTES);
    cudaFuncSetAttribute((const void*)gemm_tc<E_ELU1,true ,false,true ,false>, cudaFuncAttributeMaxDynamicSharedMemorySize, SMEM_BYTES);
    cudaFuncSetAttribute((const void*)gemm_tc<E_MASK,true ,false,true ,false>, cudaFuncAttributeMaxDynamicSharedMemorySize, SMEM_BYTES);
    cudaFuncSetAttribute((const void*)gemm_tc<E_NONE,false,false,true ,false>, cudaFuncAttributeMaxDynamicSharedMemorySize, SMEM_BYTES);
    cudaFuncSetAttribute((const void*)gemm_tc<E_NONE,false,false,false,true >, cudaFuncAttributeMaxDynamicSharedMemorySize, SMEM_BYTES);
    cudaFuncSetAttribute((const void*)gemm_tc<E_RELU,false,true ,true ,false>, cudaFuncAttributeMaxDynamicSharedMemorySize, SMEM_BYTES);

    // ---- preconvert inputs & weights to bf16 hi/lo ----
    cvt_hilo<<<(ROWS*DM/4+255)/256,256>>>(x,   xh,  xl,  ROWS*DM/4);
    cvt_hilo<<<(ROWS*DM/4+255)/256,256>>>(src, sh,  sl,  ROWS*DM/4);
    cvt_hilo<<<(DM*DM/4+255)/256,  256>>>(Wq,  Wqh, Wql, DM*DM/4);
    cvt_hilo<<<(DM*DM/4+255)/256,  256>>>(Wk,  Wkh, Wkl, DM*DM/4);
    cvt_hilo<<<(DM*DM/4+255)/256,  256>>>(Wv,  Wvh, Wvl, DM*DM/4);
    cvt_hilo<<<(DM*DM/4+255)/256,  256>>>(Wm,  Wmh, Wml, DM*DM/4);
    cvt_hilo<<<(4*DM*DM/4+255)/256,256>>>(W1,  W1h, W1l, 4*DM*DM/4);
    cvt_hilo<<<(2*DM*DM/4+255)/256,256>>>(W2,  W2h, W2l, 2*DM*DM/4);

    dim3 blk(256);

    // 1) Q = (elu(x@Wq^T)+1)*x_mask              -> hi/lo [65536,512]
    gemm_tc<E_ELU1,false,false,true,false><<<dim3(4,256,1), blk, SMEM_BYTES>>>(
        xh, xl, nullptr, nullptr, Wqh, Wql, Qh, Ql, nullptr, xm,
        DM, ROWS, 0, 0, 0, DM);
    // 2) KfT = ((elu(src@Wk^T)+1)*mask)^T        -> hi/lo [64][512][1024]
    gemm_tc<E_ELU1,true,false,true,false><<<dim3(4,256,1), blk, SMEM_BYTES>>>(
        sh, sl, nullptr, nullptr, Wkh, Wkl, KfTh, KfTl, nullptr, sm_,
        DM, ROWS, 0, 0, 0, DM);
    // 3) VfT = ((src@Wv^T)*mask)^T               -> hi/lo [64][512][1024]
    gemm_tc<E_MASK,true,false,true,false><<<dim3(4,256,1), blk, SMEM_BYTES>>>(
        sh, sl, nullptr, nullptr, Wvh, Wvl, VfTh, VfTl, nullptr, sm_,
        DM, ROWS, 0, 0, 0, DM);

    // 4) Ksum, Z  (restored: LN eps is NOT scale-invariant)
    ksumT_kernel<<<(NB*DM)/8, 256>>>(KfTh, KfTl, Ks);
    z_kernel<<<(ROWS*32)/256, 256>>>(Qh, Ql, Ks, Zb);

    // 5) KV[n][d][v] = KfT[n] @ VfT[n]^T (K=1024) -> hi/lo [64][512][512]
    gemm_tc<E_NONE,false,false,true,false><<<dim3(4,2,NB), blk, SMEM_BYTES>>>(
        KfTh, KfTl, nullptr, nullptr, VfTh, VfTl, KVh, KVl, nullptr, nullptr,
        LL, DM, (long long)DM*LL, (long long)DM*LL, (long long)DM*DM, DM);
    // 6) M[n][o][d] = Wm @ KV[n]^T (Wm folded into KV; K=512)
    gemm_tc<E_NONE,false,false,true,false><<<dim3(4,2,NB), blk, SMEM_BYTES>>>(
        Wmh, Wml, nullptr, nullptr, KVh, KVl, Mh, Ml, nullptr, nullptr,
        DM, DM, 0, (long long)DM*DM, (long long)DM*DM, DM);
    // 7) msg2 = Q[n] @ M[n]^T (unscaled; Z applied inside LN1)
    gemm_tc<E_NONE,false,false,false,true><<<dim3(4,4,NB), blk, SMEM_BYTES>>>(
        Qh, Ql, nullptr, nullptr, Mh, Ml, nullptr, nullptr, msg2f, nullptr,
        DM, LL, (long long)LL*DM, (long long)DM*DM, (long long)LL*DM, DM);

    // 8) LN1( z * msg2 ) -> bf16 hi/lo
    ln_kernel_bf<<<ROWS, 128>>>(msg2f, Zb, g1, b1, m2h, m2l);
    // 9) t = relu([x|msg2] @ W1^T)                -> hi/lo [65536,1024]
    gemm_tc<E_RELU,false,true,true,false><<<dim3(8,256,1), blk, SMEM_BYTES>>>(
        xh, xl, m2h, m2l, W1h, W1l, th, tl, nullptr, nullptr,
        2*DM, ROWS, 0, 0, 0, 2*DM);
    // 10) h2 = t @ W2^T                           -> fp32 [65536,512]
    gemm_tc<E_NONE,false,false,false,true><<<dim3(4,256,1), blk, SMEM_BYTES>>>(
        th, tl, nullptr, nullptr, W2h, W2l, nullptr, nullptr, h2f, nullptr,
        2*DM, ROWS, 0, 0, 0, DM);
    // 11) out = x + LN2(h2)
    ln_res_kernel<<<ROWS, 128>>>(h2f, x, g2, b2, out);
}

// round 13
// speedup vs baseline: 1.0022x; 1.0014x over previous
#include <cuda_runtime.h>
#include <cuda_bf16.h>
#include <mma.h>
#include <math.h>
#include <stdint.h>

using namespace nvcuda;

#define NB   64
#define LL   1024
#define DM   512
#define ROWS (NB*LL)          // 65536

// ---------------- persistent bf16 hi/lo planes + fp32 scratch -------------
__device__ __nv_bfloat16 g_xh [(size_t)ROWS*DM],  g_xl [(size_t)ROWS*DM];
__device__ __nv_bfloat16 g_sh [(size_t)ROWS*DM],  g_sl [(size_t)ROWS*DM];
__device__ __nv_bfloat16 g_Wqh[DM*DM], g_Wql[DM*DM];
__device__ __nv_bfloat16 g_Wkh[DM*DM], g_Wkl[DM*DM];
__device__ __nv_bfloat16 g_Wvh[DM*DM], g_Wvl[DM*DM];
__device__ __nv_bfloat16 g_Wmh[DM*DM], g_Wml[DM*DM];
__device__ __nv_bfloat16 g_W1h[4*DM*DM], g_W1l[4*DM*DM];
__device__ __nv_bfloat16 g_W2h[2*DM*DM], g_W2l[2*DM*DM];
__device__ __nv_bfloat16 g_Qh  [(size_t)ROWS*DM], g_Ql  [(size_t)ROWS*DM];
__device__ __nv_bfloat16 g_KfTh[(size_t)ROWS*DM], g_KfTl[(size_t)ROWS*DM];
__device__ __nv_bfloat16 g_VfTh[(size_t)ROWS*DM], g_VfTl[(size_t)ROWS*DM];
__device__ __nv_bfloat16 g_KVh [(size_t)NB*DM*DM], g_KVl [(size_t)NB*DM*DM];
__device__ __nv_bfloat16 g_Mh  [(size_t)NB*DM*DM], g_Ml  [(size_t)NB*DM*DM];
__device__ __nv_bfloat16 g_m2h [(size_t)ROWS*DM], g_m2l [(size_t)ROWS*DM];
__device__ __nv_bfloat16 g_th  [(size_t)ROWS*2*DM], g_tl [(size_t)ROWS*2*DM];
__device__ float g_msg2f[(size_t)ROWS*DM];
__device__ float g_h2f  [(size_t)ROWS*DM];
__device__ float g_Ksum [NB*DM];
__device__ float g_Z    [ROWS];

enum { E_NONE=0, E_ELU1=1, E_MASK=2, E_RELU=4 };

// smem: 3 stages; each stage = Ahi(20480) Alo(20480) Bhi(10240) Blo(10240)
#define BK    32
#define LDAB  40
#define SSZ   61440
#define SMEM_BYTES 184320
#define LDST  132
#define LDST_T 264

__device__ __forceinline__ void cpa16(uint32_t dst, const void* src){
    asm volatile("cp.async.cg.shared.global [%0], [%1], 16;" :: "r"(dst), "l"(src) : "memory");
}
#define CP_COMMIT() asm volatile("cp.async.commit_group;" ::: "memory")

__device__ __forceinline__ void hilo(float x, __nv_bfloat16& h, __nv_bfloat16& l){
    h = __float2bfloat16_rn(x);
    l = __float2bfloat16_rn(x - __bfloat162float(h));
}

// =====================================================================
// bf16 3-term split NT GEMM (cp.async 3-stage): C = A @ B^T, K-major
// CTA tile 256x128, BK=32, 256 thr / 8 warps, warp tile 64x64
// =====================================================================
template<int EPI, bool TRANSC, bool CAT, bool OBF, bool OF32>
__global__ void __launch_bounds__(256)
gemm_tc(const __nv_bfloat16* __restrict__ A1h, const __nv_bfloat16* __restrict__ A1l,
        const __nv_bfloat16* __restrict__ A2h, const __nv_bfloat16* __restrict__ A2l,
        const __nv_bfloat16* __restrict__ Bh,  const __nv_bfloat16* __restrict__ Bl,
        __nv_bfloat16* __restrict__ Ch, __nv_bfloat16* __restrict__ Cl,
        float* __restrict__ Cf, const float* __restrict__ rs,
        int K, int M_batch, long long a_bs, long long b_bs, long long c_bs, int nld)
{
    extern __shared__ char smx[];
    const uint32_t sb = (uint32_t)__cvta_generic_to_shared(smx);
    const int tid  = threadIdx.x;
    const int wid  = tid >> 5;
    const int lane = tid & 31;
    const int wm   = wid & 3;          // 64-row block
    const int wn   = wid >> 2;         // 64-col block
    const int bm   = blockIdx.y * 256;
    const int bn   = blockIdx.x * 128;
    const int z    = blockIdx.z;
    const __nv_bfloat16* Abh = A1h + (size_t)z * a_bs;
    const __nv_bfloat16* Abl = A1l + (size_t)z * a_bs;
    const __nv_bfloat16* Bbh = Bh  + (size_t)z * b_bs;
    const __nv_bfloat16* Bbl = Bl  + (size_t)z * b_bs;

    wmma::fragment<wmma::accumulator,16,16,16,float> acc[4][4];
#pragma unroll
    for (int i=0;i<4;i++)
#pragma unroll
        for (int j=0;j<4;j++) wmma::fill_fragment(acc[i][j], 0.f);

    const int KT = K / BK;

    auto ISSUE = [&](int kt, int buf){
        const int k0 = kt * BK;
        const uint32_t base = sb + buf * SSZ;
#pragma unroll
        for (int p=0;p<2;p++){
#pragma unroll
            for (int i=0;i<4;i++){
                int idx = tid + i*256;
                int r = idx >> 2, c = idx & 3;
                int kk = k0 + c*8;
                const __nv_bfloat16* src;
                if (CAT){
                    const __nv_bfloat16* bp = (kk < DM) ? (p ? A1l : A1h)
                                                        : (p ? A2l : A2h);
                    int kkk = (kk < DM) ? kk : kk - DM;
                    src = bp + (size_t)(bm+r)*DM + kkk;
                } else {
                    src = (p ? Abl : Abh) + (size_t)(bm+r)*K + kk;
                }
                cpa16(base + p*20480 + r*80 + c*16, src);
            }
        }
#pragma unroll
        for (int p=0;p<2;p++){
#pragma unroll
            for (int i=0;i<2;i++){
                int idx = tid + i*256;
                int r = idx >> 2, c = idx & 3;
                int kk = k0 + c*8;
                const __nv_bfloat16* src = (p ? Bbl : Bbh) + (size_t)(bn+r)*K + kk;
                cpa16(base + 40960 + p*10240 + r*80 + c*16, src);
            }
        }
    };

    auto COMPUTE = [&](int buf){
        const __nv_bfloat16* Ah_ = (const __nv_bfloat16*)(smx + buf*SSZ);
        const __nv_bfloat16* Al_ = (const __nv_bfloat16*)(smx + buf*SSZ + 20480);
        const __nv_bfloat16* Bh_ = (const __nv_bfloat16*)(smx + buf*SSZ + 40960);
        const __nv_bfloat16* Bl_ = (const __nv_bfloat16*)(smx + buf*SSZ + 51200);
#pragma unroll
        for (int ks=0; ks<2; ks++){
            wmma::fragment<wmma::matrix_b,16,16,16,__nv_bfloat16,wmma::col_major> fbh[4], fbl[4];
#pragma unroll
            for (int j=0;j<4;j++){
                wmma::load_matrix_sync(fbh[j], Bh_ + (wn*64+j*16)*LDAB + ks*16, LDAB);
                wmma::load_matrix_sync(fbl[j], Bl_ + (wn*64+j*16)*LDAB + ks*16, LDAB);
            }
#pragma unroll
            for (int i=0;i<4;i++){
                wmma::fragment<wmma::matrix_a,16,16,16,__nv_bfloat16,wmma::row_major> fah, fal;
                wmma::load_matrix_sync(fah, Ah_ + (wm*64+i*16)*LDAB + ks*16, LDAB);
                wmma::load_matrix_sync(fal, Al_ + (wm*64+i*16)*LDAB + ks*16, LDAB);
#pragma unroll
                for (int j=0;j<4;j++){
                    wmma::mma_sync(acc[i][j], fah, fbh[j], acc[i][j]);
                    wmma::mma_sync(acc[i][j], fah, fbl[j], acc[i][j]);
                    wmma::mma_sync(acc[i][j], fal, fbh[j], acc[i][j]);
                }
            }
        }
    };

    ISSUE(0,0); CP_COMMIT();
    ISSUE(1,1); CP_COMMIT();

    for (int kt=0; kt<KT; kt++){
        if (kt < KT-1) asm volatile("cp.async.wait_group 1;" ::: "memory");
        else           asm volatile("cp.async.wait_group 0;" ::: "memory");
        __syncthreads();
        if (kt+2 < KT){ ISSUE(kt+2, (kt+2)%3); CP_COMMIT(); }
        COMPUTE(kt % 3);
    }
    __syncthreads();

    // ---------------- epilogue via smem stage ----------------
    float* stage = (float*)smx;
#pragma unroll
    for (int i=0;i<4;i++)
#pragma unroll
        for (int j=0;j<4;j++){
            if (!TRANSC)
                wmma::store_matrix_sync(stage + (wm*64+i*16)*LDST + wn*64 + j*16,
                                        acc[i][j], LDST, wmma::mem_row_major);
            else
                wmma::store_matrix_sync(stage + (wn*64+j*16)*LDST_T + wm*64 + i*16,
                                        acc[i][j], LDST_T, wmma::mem_col_major);
        }
    __syncthreads();

    if (!TRANSC){
#pragma unroll
        for (int i=0;i<32;i++){
            int r  = wid*32 + i;
            int gm = bm + r;
            size_t grow = (size_t)z * M_batch + gm;
            float scale = 1.f;
            if (EPI==E_ELU1 || EPI==E_MASK) scale = rs[grow];
            float4 v = *(const float4*)(stage + r*LDST + lane*4);
            float o[4] = {v.x, v.y, v.z, v.w};
#pragma unroll
            for (int c=0;c<4;c++){
                float xx = o[c];
                if      (EPI==E_ELU1) xx = (xx > 0.f ? xx + 1.f : expf(xx)) * scale;
                else if (EPI==E_MASK) xx = xx * scale;
                else if (EPI==E_RELU) xx = fmaxf(xx, 0.f);
                o[c] = xx;
            }
            size_t coff = (size_t)z*c_bs + (size_t)gm*nld + bn + lane*4;
            if (OF32){
                float4 w = {o[0],o[1],o[2],o[3]};
                *(float4*)(Cf + coff) = w;
            }
            if (OBF){
                __nv_bfloat16 h[4], l[4];
#pragma unroll
                for (int c=0;c<4;c++) hilo(o[c], h[c], l[c]);
                *(__nv_bfloat162*)(Ch + coff)     = __nv_bfloat162(h[0],h[1]);
                *(__nv_bfloat162*)(Ch + coff + 2) = __nv_bfloat162(h[2],h[3]);
                *(__nv_bfloat162*)(Cl + coff)     = __nv_bfloat162(l[0],l[1]);
                *(__nv_bfloat162*)(Cl + coff + 2) = __nv_bfloat162(l[2],l[3]);
            }
        }
    } else {
        // transposed per-batch store: CT[n][col][s]; batch n fixed per tile
        const int s0 = bm & (LL-1);
        const int n  = bm >> 10;
#pragma unroll
        for (int cc=0; cc<16; cc++){
            int c = wid*16 + cc;
#pragma unroll
            for (int seg=0; seg<2; seg++){
                int rr = seg*128 + lane*4;
                float4 v = *(const float4*)(stage + c*LDST_T + rr);
                float o[4] = {v.x, v.y, v.z, v.w};
                if (EPI==E_ELU1 || EPI==E_MASK){
                    float4 sc = *(const float4*)(rs + bm + rr);
                    float s[4] = {sc.x, sc.y, sc.z, sc.w};
#pragma unroll
                    for (int ct=0;ct<4;ct++){
                        float xx = o[ct];
                        if (EPI==E_ELU1) xx = (xx > 0.f ? xx + 1.f : expf(xx)) * s[ct];
                        else             xx = xx * s[ct];
                        o[ct] = xx;
                    }
                }
                size_t coff = (size_t)n*DM*LL + (size_t)(bn + c)*LL + s0 + rr;
                __nv_bfloat16 h[4], l[4];
#pragma unroll
                for (int ct=0;ct<4;ct++) hilo(o[ct], h[ct], l[ct]);
                *(__nv_bfloat162*)(Ch + coff)     = __nv_bfloat162(h[0],h[1]);
                *(__nv_bfloat162*)(Ch + coff + 2) = __nv_bfloat162(h[2],h[3]);
                *(__nv_bfloat162*)(Cl + coff)     = __nv_bfloat162(l[0],l[1]);
                *(__nv_bfloat162*)(Cl + coff + 2) = __nv_bfloat162(l[2],l[3]);
            }
        }
    }
}

// ---------------- fp32 -> bf16 hi/lo converter ----------------------------
__global__ void cvt_hilo(const float* __restrict__ in,
                         __nv_bfloat16* __restrict__ hi,
                         __nv_bfloat16* __restrict__ lo, int n4)
{
    int i = blockIdx.x*blockDim.x + threadIdx.x;
    if (i >= n4) return;
    float4 v = ((const float4*)in)[i];
    __nv_bfloat16 h[4], l[4];
    hilo(v.x,h[0],l[0]); hilo(v.y,h[1],l[1]); hilo(v.z,h[2],l[2]); hilo(v.w,h[3],l[3]);
    ((__nv_bfloat162*)hi)[2*i]   = __nv_bfloat162(h[0],h[1]);
    ((__nv_bfloat162*)hi)[2*i+1] = __nv_bfloat162(h[2],h[3]);
    ((__nv_bfloat162*)lo)[2*i]   = __nv_bfloat162(l[0],l[1]);
    ((__nv_bfloat162*)lo)[2*i+1] = __nv_bfloat162(l[2],l[3]);
}

// ---------------- Ksum: Ks[n*512+d] = sum_s KfT[n][d][s] ------------------
__global__ void ksumT_kernel(const __nv_bfloat16* __restrict__ h,
                             const __nv_bfloat16* __restrict__ l,
                             float* __restrict__ Ks)
{
    int wid = threadIdx.x >> 5, lane = threadIdx.x & 31;
    int row = blockIdx.x * 8 + wid;
    const __nv_bfloat162* ph = (const __nv_bfloat162*)(h + (size_t)row * LL);
    const __nv_bfloat162* pl = (const __nv_bfloat162*)(l + (size_t)row * LL);
    float s = 0.f;
#pragma unroll
    for (int i = 0; i < 16; i++){
        __nv_bfloat162 a = ph[lane + i*32], b = pl[lane + i*32];
        s += __bfloat162float(a.x)+__bfloat162float(a.y)
           + __bfloat162float(b.x)+__bfloat162float(b.y);
    }
#pragma unroll
    for (int o = 16; o; o >>= 1) s += __shfl_xor_sync(0xffffffffu, s, o);
    if (!lane) Ks[row] = s;
}

// ---------------- Z: Z[r] = 1/(dot(Q[r], Ksum[n]) + 1e-6) -----------------
__global__ void z_kernel(const __nv_bfloat16* __restrict__ Qh,
                         const __nv_bfloat16* __restrict__ Ql,
                         const float* __restrict__ Ks, float* __restrict__ Z)
{
    int gw   = (blockIdx.x*blockDim.x + threadIdx.x) >> 5;
    int lane = threadIdx.x & 31;
    if (gw >= ROWS) return;
    int n = gw >> 10;
    const __nv_bfloat16* qh = Qh + (size_t)gw*DM;
    const __nv_bfloat16* ql = Ql + (size_t)gw*DM;
    const float* k = Ks + n*DM;
    float s = 0.f;
#pragma unroll
    for (int i = 0; i < DM/32; i++){
        int d = lane + i*32;
        float q = __bfloat162float(qh[d]) + __bfloat162float(ql[d]);
        s = fmaf(q, k[d], s);
    }
#pragma unroll
    for (int off = 16; off; off >>= 1) s += __shfl_xor_sync(0xffffffffu, s, off);
    if (lane == 0) Z[gw] = 1.f / (s + 1e-6f);
}

// ------- LayerNorm of (z[row] * in[row,:]) -> bf16 hi/lo out ---------------
__global__ void ln_kernel_bf(const float* __restrict__ in,
                             const float* __restrict__ Z,
                             const float* __restrict__ g, const float* __restrict__ b,
                             __nv_bfloat16* __restrict__ oh, __nv_bfloat16* __restrict__ ol)
{
    int row = blockIdx.x;
    int tid = threadIdx.x;
    float zr = Z[row];
    float4 v = *(const float4*)(in + (size_t)row*DM + tid*4);
    v.x *= zr; v.y *= zr; v.z *= zr; v.w *= zr;
    __shared__ float red[128];
    red[tid] = v.x + v.y + v.z + v.w;
    __syncthreads();
    for (int off = 64; off; off >>= 1) { if (tid < off) red[tid] += red[tid+off]; __syncthreads(); }
    float mu = red[0] * (1.f/DM);
    __syncthreads();
    float dx = v.x-mu, dy = v.y-mu, dz = v.z-mu, dw = v.w-mu;
    red[tid] = dx*dx + dy*dy + dz*dz + dw*dw;
    __syncthreads();
    for (int off = 64; off; off >>= 1) { if (tid < off) red[tid] += red[tid+off]; __syncthreads(); }
    float rstd = rsqrtf(red[0] * (1.f/DM) + 1e-5f);
    float4 gv = *(const float4*)(g + tid*4);
    float4 bv = *(const float4*)(b + tid*4);
    float o0 = dx*rstd*gv.x + bv.x, o1 = dy*rstd*gv.y + bv.y;
    float o2 = dz*rstd*gv.z + bv.z, o3 = dw*rstd*gv.w + bv.w;
    __nv_bfloat16 h[4], l[4];
    hilo(o0,h[0],l[0]); hilo(o1,h[1],l[1]); hilo(o2,h[2],l[2]); hilo(o3,h[3],l[3]);
    size_t off4 = (size_t)row*DM + tid*4;
    *(__nv_bfloat162*)(oh + off4)     = __nv_bfloat162(h[0],h[1]);
    *(__nv_bfloat162*)(oh + off4 + 2) = __nv_bfloat162(h[2],h[3]);
    *(__nv_bfloat162*)(ol + off4)     = __nv_bfloat162(l[0],l[1]);
    *(__nv_bfloat162*)(ol + off4 + 2) = __nv_bfloat162(l[2],l[3]);
}

// ---------------- out = x + LN(h2) (all fp32) ------------------------------
__global__ void ln_res_kernel(const float* __restrict__ in,
                              const float* __restrict__ x,
                              const float* __restrict__ g, const float* __restrict__ b,
                              float* __restrict__ out)
{
    int row = blockIdx.x;
    int tid = threadIdx.x;
    float4 v = *(const float4*)(in + (size_t)row*DM + tid*4);
    __shared__ float red[128];
    red[tid] = v.x + v.y + v.z + v.w;
    __syncthreads();
    for (int off = 64; off; off >>= 1) { if (tid < off) red[tid] += red[tid+off]; __syncthreads(); }
    float mu = red[0] * (1.f/DM);
    __syncthreads();
    float dx = v.x-mu, dy = v.y-mu, dz = v.z-mu, dw = v.w-mu;
    red[tid] = dx*dx + dy*dy + dz*dz + dw*dw;
    __syncthreads();
    for (int off = 64; off; off >>= 1) { if (tid < off) red[tid] += red[tid+off]; __syncthreads(); }
    float rstd = rsqrtf(red[0] * (1.f/DM) + 1e-5f);
    float4 gv = *(const float4*)(g + tid*4);
    float4 bv = *(const float4*)(b + tid*4);
    float4 xv = *(const float4*)(x + (size_t)row*DM + tid*4);
    float4 o;
    o.x = xv.x + dx*rstd*gv.x + bv.x; o.y = xv.y + dy*rstd*gv.y + bv.y;
    o.z = xv.z + dz*rstd*gv.z + bv.z; o.w = xv.w + dw*rstd*gv.w + bv.w;
    *(float4*)(out + (size_t)row*DM + tid*4) = o;
}

// =====================================================================
extern "C" void kernel_launch(void* const* d_in, const int* in_sizes, int n_in,
                              void* d_out, int out_size)
{
    const float* x   = (const float*)d_in[0];
    const float* src = (const float*)d_in[1];
    const float* Wq  = (const float*)d_in[2];
    const float* Wk  = (const float*)d_in[3];
    const float* Wv  = (const float*)d_in[4];
    const float* Wm  = (const float*)d_in[5];
    const float* W1  = (const float*)d_in[6];
    const float* W2  = (const float*)d_in[7];
    const float* g1  = (const float*)d_in[8];
    const float* b1  = (const float*)d_in[9];
    const float* g2  = (const float*)d_in[10];
    const float* b2  = (const float*)d_in[11];
    const float* xm  = (const float*)d_in[12];
    const float* sm_ = (const float*)d_in[13];
    float* out = (float*)d_out;

    __nv_bfloat16 *xh,*xl,*sh,*sl,*Wqh,*Wql,*Wkh,*Wkl,*Wvh,*Wvl,*Wmh,*Wml,*W1h,*W1l,*W2h,*W2l;
    __nv_bfloat16 *Qh,*Ql,*KfTh,*KfTl,*VfTh,*VfTl,*KVh,*KVl,*Mh,*Ml,*m2h,*m2l,*th,*tl;
    float *msg2f,*h2f,*Ks,*Zb;
    cudaGetSymbolAddress((void**)&xh, g_xh);   cudaGetSymbolAddress((void**)&xl, g_xl);
    cudaGetSymbolAddress((void**)&sh, g_sh);   cudaGetSymbolAddress((void**)&sl, g_sl);
    cudaGetSymbolAddress((void**)&Wqh,g_Wqh);  cudaGetSymbolAddress((void**)&Wql,g_Wql);
    cudaGetSymbolAddress((void**)&Wkh,g_Wkh);  cudaGetSymbolAddress((void**)&Wkl,g_Wkl);
    cudaGetSymbolAddress((void**)&Wvh,g_Wvh);  cudaGetSymbolAddress((void**)&Wvl,g_Wvl);
    cudaGetSymbolAddress((void**)&Wmh,g_Wmh);  cudaGetSymbolAddress((void**)&Wml,g_Wml);
    cudaGetSymbolAddress((void**)&W1h,g_W1h);  cudaGetSymbolAddress((void**)&W1l,g_W1l);
    cudaGetSymbolAddress((void**)&W2h,g_W2h);  cudaGetSymbolAddress((void**)&W2l,g_W2l);
    cudaGetSymbolAddress((void**)&Qh, g_Qh);   cudaGetSymbolAddress((void**)&Ql, g_Ql);
    cudaGetSymbolAddress((void**)&KfTh,g_KfTh);cudaGetSymbolAddress((void**)&KfTl,g_KfTl);
    cudaGetSymbolAddress((void**)&VfTh,g_VfTh);cudaGetSymbolAddress((void**)&VfTl,g_VfTl);
    cudaGetSymbolAddress((void**)&KVh, g_KVh); cudaGetSymbolAddress((void**)&KVl, g_KVl);
    cudaGetSymbolAddress((void**)&Mh,  g_Mh);  cudaGetSymbolAddress((void**)&Ml,  g_Ml);
    cudaGetSymbolAddress((void**)&m2h, g_m2h); cudaGetSymbolAddress((void**)&m2l, g_m2l);
    cudaGetSymbolAddress((void**)&th,  g_th);  cudaGetSymbolAddress((void**)&tl,  g_tl);
    cudaGetSymbolAddress((void**)&msg2f,g_msg2f);
    cudaGetSymbolAddress((void**)&h2f, g_h2f);
    cudaGetSymbolAddress((void**)&Ks,  g_Ksum);
    cudaGetSymbolAddress((void**)&Zb,  g_Z);

    cudaFuncSetAttribute((const void*)gemm_tc<E_ELU1,false,false,true ,false>, cudaFuncAttributeMaxDynamicSharedMemorySize, SMEM_BYTES);
    cudaFuncSetAttribute((const void*)gemm_tc<E_ELU1,true ,false,true ,false>, cudaFuncAttributeMaxDynamicSharedMemorySize, SMEM_BYTES);
    cudaFuncSetAttribute((const void*)gemm_tc<E_MASK,true ,false,true ,false>, cudaFuncAttributeMaxDynamicSharedMemorySize, SMEM_BYTES);
    cudaFuncSetAttribute((const void*)gemm_tc<E_NONE,false,false,true ,false>, cudaFuncAttributeMaxDynamicSharedMemorySize, SMEM_BYTES);
    cudaFuncSetAttribute((const void*)gemm_tc<E_NONE,false,false,false,true >, cudaFuncAttributeMaxDynamicSharedMemorySize, SMEM_BYTES);
    cudaFuncSetAttribute((const void*)gemm_tc<E_RELU,false,true ,true ,false>, cudaFuncAttributeMaxDynamicSharedMemorySize, SMEM_BYTES);

    // ---- preconvert inputs & weights to bf16 hi/lo ----
    cvt_hilo<<<(ROWS*DM/4+255)/256,256>>>(x,   xh,  xl,  ROWS*DM/4);
    cvt_hilo<<<(ROWS*DM/4+255)/256,256>>>(src, sh,  sl,  ROWS*DM/4);
    cvt_hilo<<<(DM*DM/4+255)/256,  256>>>(Wq,  Wqh, Wql, DM*DM/4);
    cvt_hilo<<<(DM*DM/4+255)/256,  256>>>(Wk,  Wkh, Wkl, DM*DM/4);
    cvt_hilo<<<(DM*DM/4+255)/256,  256>>>(Wv,  Wvh, Wvl, DM*DM/4);
    cvt_hilo<<<(DM*DM/4+255)/256,  256>>>(Wm,  Wmh, Wml, DM*DM/4);
    cvt_hilo<<<(4*DM*DM/4+255)/256,256>>>(W1,  W1h, W1l, 4*DM*DM/4);
    cvt_hilo<<<(2*DM*DM/4+255)/256,256>>>(W2,  W2h, W2l, 2*DM*DM/4);

    dim3 blk(256);

    // 1) Q = (elu(x@Wq^T)+1)*x_mask              -> hi/lo [65536,512]
    gemm_tc<E_ELU1,false,false,true,false><<<dim3(4,256,1), blk, SMEM_BYTES>>>(
        xh, xl, nullptr, nullptr, Wqh, Wql, Qh, Ql, nullptr, xm,
        DM, ROWS, 0, 0, 0, DM);
    // 2) KfT = ((elu(src@Wk^T)+1)*mask)^T        -> hi/lo [64][512][1024]
    gemm_tc<E_ELU1,true,false,true,false><<<dim3(4,256,1), blk, SMEM_BYTES>>>(
        sh, sl, nullptr, nullptr, Wkh, Wkl, KfTh, KfTl, nullptr, sm_,
        DM, ROWS, 0, 0, 0, DM);
    // 3) VfT = ((src@Wv^T)*mask)^T               -> hi/lo [64][512][1024]
    gemm_tc<E_MASK,true,false,true,false><<<dim3(4,256,1), blk, SMEM_BYTES>>>(
        sh, sl, nullptr, nullptr, Wvh, Wvl, VfTh, VfTl, nullptr, sm_,
        DM, ROWS, 0, 0, 0, DM);

    // 4) Ksum, Z  (restored: LN eps is NOT scale-invariant)
    ksumT_kernel<<<(NB*DM)/8, 256>>>(KfTh, KfTl, Ks);
    z_kernel<<<(ROWS*32)/256, 256>>>(Qh, Ql, Ks, Zb);

    // 5) KV[n][d][v] = KfT[n] @ VfT[n]^T (K=1024) -> hi/lo [64][512][512]
    gemm_tc<E_NONE,false,false,true,false><<<dim3(4,2,NB), blk, SMEM_BYTES>>>(
        KfTh, KfTl, nullptr, nullptr, VfTh, VfTl, KVh, KVl, nullptr, nullptr,
        LL, DM, (long long)DM*LL, (long long)DM*LL, (long long)DM*DM, DM);
    // 6) M[n][o][d] = Wm @ KV[n]^T (Wm folded into KV; K=512)
    gemm_tc<E_NONE,false,false,true,false><<<dim3(4,2,NB), blk, SMEM_BYTES>>>(
        Wmh, Wml, nullptr, nullptr, KVh, KVl, Mh, Ml, nullptr, nullptr,
        DM, DM, 0, (long long)DM*DM, (long long)DM*DM, DM);
    // 7) msg2 = Q[n] @ M[n]^T (unscaled; Z applied inside LN1)
    gemm_tc<E_NONE,false,false,false,true><<<dim3(4,4,NB), blk, SMEM_BYTES>>>(
        Qh, Ql, nullptr, nullptr, Mh, Ml, nullptr, nullptr, msg2f, nullptr,
        DM, LL, (long long)LL*DM, (long long)DM*DM, (long long)LL*DM, DM);

    // 8) LN1( z * msg2 ) -> bf16 hi/lo
    ln_kernel_bf<<<ROWS, 128>>>(msg2f, Zb, g1, b1, m2h, m2l);
    // 9) t = relu([x|msg2] @ W1^T)                -> hi/lo [65536,1024]
    gemm_tc<E_RELU,false,true,true,false><<<dim3(8,256,1), blk, SMEM_BYTES>>>(
        xh, xl, m2h, m2l, W1h, W1l, th, tl, nullptr, nullptr,
        2*DM, ROWS, 0, 0, 0, 2*DM);
    // 10) h2 = t @ W2^T                           -> fp32 [65536,512]
    gemm_tc<E_NONE,false,false,false,true><<<dim3(4,256,1), blk, SMEM_BYTES>>>(
        th, tl, nullptr, nullptr, W2h, W2l, nullptr, nullptr, h2f, nullptr,
        2*DM, ROWS, 0, 0, 0, DM);
    // 11) out = x + LN2(h2)
    ln_res_kernel<<<ROWS, 128>>>(h2f, x, g2, b2, out);
}